// round 10
// baseline (speedup 1.0000x reference)
#include <cuda_runtime.h>
#include <cuda_fp16.h>
#include <math.h>
#include <stdint.h>

// ---------------- problem constants ----------------
#define NU 100000
#define NR 50000
#define NE 1000000
#define EP 500000
#define EN 500000
#define IN_U 128
#define IN_R 256
#define D0 128
#define DH 128
#define DOUT 64

#define NBU_C 98   // ceil(NU/1024)
#define NBR_C 49   // ceil(NR/1024)

// ---------------- static scratch ----------------
__device__ __half g_spu[(size_t)NU * DOUT];
__device__ __half g_spr[(size_t)NR * DOUT];
__device__ __half g_st2_repo[(size_t)NR * DOUT];
__device__ __half g_st2_user[(size_t)NU * DOUT];
__device__ __half g_h2_user[(size_t)NU * DOUT];
__device__ __half g_h2_repo[(size_t)NR * DOUT];
__device__ int   g_deg_u[NU];
__device__ int   g_deg_r[NR];
__device__ float g_rs_u[NU];
__device__ float g_rs_r[NR];
__device__ int   g_off_u[NU];
__device__ int   g_off_r[NR];
__device__ int   g_cur_u[NU];
__device__ int   g_cur_r[NR];
__device__ int   g_csr_u[NE];
__device__ int   g_csr_r[NE];
__device__ int   g_part_u[256];
__device__ int   g_part_r[256];
// folded weights / biases
__device__ float g_T2[D0 * DOUT];
__device__ float g_Wfu2[DH * DOUT];
__device__ float g_Wfr[IN_U * DOUT];
__device__ float g_Wfpr[IN_R * DOUT];
__device__ float g_c0r[DOUT];
__device__ float g_c0u[DOUT];
__device__ float g_c1r[DOUT];
__device__ float g_bfpr[DOUT];

// ---------------- stream/event context (static-init; no device mem APIs) ----------------
struct HxStreams {
    cudaStream_t s2;
    cudaEvent_t evFork, evDeg, evGemm;
    HxStreams() {
        cudaStreamCreateWithFlags(&s2, cudaStreamNonBlocking);
        cudaEventCreateWithFlags(&evFork, cudaEventDisableTiming);
        cudaEventCreateWithFlags(&evDeg, cudaEventDisableTiming);
        cudaEventCreateWithFlags(&evGemm, cudaEventDisableTiming);
    }
};
static HxStreams g_hx;

// ---------------- degree count (2 edges per thread) ----------------
__global__ void count_deg_kernel(const int* __restrict__ e_src,
                                 const int* __restrict__ e_dst,
                                 int* __restrict__ deg_u,
                                 int* __restrict__ deg_r) {
    int i = (blockIdx.x * blockDim.x + threadIdx.x) * 2;
    if (i + 1 < NE) {
        int2 s2v = *reinterpret_cast<const int2*>(e_src + i);
        int2 d2v = *reinterpret_cast<const int2*>(e_dst + i);
        atomicAdd(&deg_u[s2v.x], 1);
        atomicAdd(&deg_u[s2v.y], 1);
        atomicAdd(&deg_r[d2v.x], 1);
        atomicAdd(&deg_r[d2v.y], 1);
    } else if (i < NE) {
        atomicAdd(&deg_u[e_src[i]], 1);
        atomicAdd(&deg_r[e_dst[i]], 1);
    }
}

__global__ void deg_to_rs2_kernel(const int* __restrict__ deg_u, const int* __restrict__ deg_r,
                                  float* __restrict__ rs_u, float* __restrict__ rs_r) {
    int i = blockIdx.x * blockDim.x + threadIdx.x;
    if (i < NU) {
        int d = deg_u[i];
        rs_u[i] = rsqrtf((float)(d > 1 ? d : 1));
    } else if (i < NU + NR) {
        int j = i - NU;
        int d = deg_r[j];
        rs_r[j] = rsqrtf((float)(d > 1 ? d : 1));
    }
}

// ---------------- batched exclusive scans (warp-shuffle) ----------------
__global__ void scan_blocks2_kernel(const int* __restrict__ deg_u, const int* __restrict__ deg_r,
                                    int* __restrict__ off_u, int* __restrict__ off_r,
                                    int* __restrict__ part_u, int* __restrict__ part_r) {
    __shared__ int wsum[32];
    int b = blockIdx.x;
    const int* in;
    int* out;
    int* partials;
    int n, lb;
    if (b < NBU_C) { in = deg_u; out = off_u; partials = part_u; n = NU; lb = b; }
    else           { in = deg_r; out = off_r; partials = part_r; n = NR; lb = b - NBU_C; }
    int tid = threadIdx.x;
    int lane = tid & 31;
    int wid = tid >> 5;
    int gid = lb * 1024 + tid;
    int v = (gid < n) ? in[gid] : 0;

    int x = v;
#pragma unroll
    for (int o = 1; o < 32; o <<= 1) {
        int t = __shfl_up_sync(0xFFFFFFFFu, x, o);
        if (lane >= o) x += t;
    }
    if (lane == 31) wsum[wid] = x;
    __syncthreads();
    if (wid == 0) {
        int w = wsum[lane];
        int y = w;
#pragma unroll
        for (int o = 1; o < 32; o <<= 1) {
            int t = __shfl_up_sync(0xFFFFFFFFu, y, o);
            if (lane >= o) y += t;
        }
        wsum[lane] = y - w;   // exclusive warp offsets
    }
    __syncthreads();
    int incl = x + wsum[wid];
    if (gid < n) out[gid] = incl - v;   // exclusive
    if (tid == 1023) partials[lb] = incl;
}

__global__ void scan_partials2_kernel(int* __restrict__ part_u, int* __restrict__ part_r) {
    __shared__ int s[128];
    int* partials = (blockIdx.x == 0) ? part_u : part_r;
    int nb = (blockIdx.x == 0) ? NBU_C : NBR_C;
    int tid = threadIdx.x;
    int v = (tid < nb) ? partials[tid] : 0;
    s[tid] = v;
    __syncthreads();
#pragma unroll
    for (int o = 1; o < 128; o <<= 1) {
        int t = (tid >= o) ? s[tid - o] : 0;
        __syncthreads();
        s[tid] += t;
        __syncthreads();
    }
    if (tid < nb) partials[tid] = s[tid] - v;
}

__global__ void scan_add2_kernel(int* __restrict__ off_u, int* __restrict__ off_r,
                                 const int* __restrict__ part_u, const int* __restrict__ part_r,
                                 int* __restrict__ cur_u, int* __restrict__ cur_r) {
    int b = blockIdx.x;
    int* out;
    int* cur;
    const int* partials;
    int n, lb;
    if (b < NBU_C) { out = off_u; cur = cur_u; partials = part_u; n = NU; lb = b; }
    else           { out = off_r; cur = cur_r; partials = part_r; n = NR; lb = b - NBU_C; }
    int gid = lb * 1024 + threadIdx.x;
    if (gid < n) {
        int v = out[gid] + partials[lb];
        out[gid] = v;
        cur[gid] = v;
    }
}

// ---------------- CSR fill ----------------
__global__ void fill_csr_kernel(const int* __restrict__ e_src, const int* __restrict__ e_dst,
                                int* __restrict__ cur_u, int* __restrict__ cur_r,
                                int* __restrict__ csr_u, int* __restrict__ csr_r, int E) {
    int i = blockIdx.x * blockDim.x + threadIdx.x;
    if (i < E) {
        int s = e_src[i];
        int d = e_dst[i];
        int pr = atomicAdd(&cur_r[d], 1);
        csr_r[pr] = s;
        int pu = atomicAdd(&cur_u[s], 1);
        csr_u[pu] = d;
    }
}

// ---------------- batched fold: up to 4 jobs of C[M,64] = A[M,128] @ B[128,64] ----------------
struct FoldJobs {
    const float* A[4];
    const float* B[4];
    float* C[4];
    int M[4];
    int boff[5];
};

__global__ void fold4_kernel(FoldJobs jobs) {
    int bx = blockIdx.x;
    int j = 0;
    while (j < 3 && bx >= jobs.boff[j + 1]) j++;
    const float* A = jobs.A[j];
    const float* B = jobs.B[j];
    float* C = jobs.C[j];
    int M = jobs.M[j];
    int m0 = (bx - jobs.boff[j]) * 4;

    __shared__ float sA[4][128];
    int tx = threadIdx.x;
    int ty = threadIdx.y;
    int tid = ty * 64 + tx;
    for (int i = tid; i < 4 * 128; i += 256) {
        int r = i >> 7, k = i & 127;
        sA[r][k] = (m0 + r < M) ? A[(size_t)(m0 + r) * 128 + k] : 0.0f;
    }
    __syncthreads();
    int m = m0 + ty;
    if (m >= M) return;
    float acc0 = 0.f, acc1 = 0.f;
#pragma unroll
    for (int k = 0; k < 128; k += 2) {
        acc0 = fmaf(sA[ty][k], B[k * 64 + tx], acc0);
        acc1 = fmaf(sA[ty][k + 1], B[(k + 1) * 64 + tx], acc1);
    }
    C[(size_t)m * 64 + tx] = acc0 + acc1;
}

// ---------------- fp16 helpers ----------------
__device__ __forceinline__ void acc_add8(float* acc, uint4 x) {
    const __half2* p = reinterpret_cast<const __half2*>(&x);
#pragma unroll
    for (int i = 0; i < 4; i++) {
        float2 f = __half22float2(p[i]);
        acc[2 * i] += f.x;
        acc[2 * i + 1] += f.y;
    }
}

// ---------------- dual-job 64-wide fp16 CSR aggregation, fused epilogues ----------------
// sources PRE-SCALED by rs_src. 8 lanes/node, 8-deep MLP, index prefetch pipeline.
template <bool NORM>
__global__ __launch_bounds__(256)
void agg64dual_kernel(const __half* __restrict__ h0, const int* __restrict__ csr0,
                      const int* __restrict__ off0, const int* __restrict__ deg0,
                      const float* __restrict__ rs0, const float* __restrict__ cvec0,
                      __half* __restrict__ out0, int n0, int nb0,
                      const __half* __restrict__ h1, const int* __restrict__ csr1,
                      const int* __restrict__ off1, const int* __restrict__ deg1,
                      const float* __restrict__ rs1, const float* __restrict__ cvec1,
                      __half* __restrict__ out1, int n1) {
    const __half* h;
    const int *csr, *off, *deg;
    const float *rs, *cvec;
    __half* outp;
    int n, gid;
    if ((int)blockIdx.x < nb0) {
        h = h0; csr = csr0; off = off0; deg = deg0; rs = rs0; cvec = cvec0;
        outp = out0; n = n0;
        gid = blockIdx.x * 256 + threadIdx.x;
    } else {
        h = h1; csr = csr1; off = off1; deg = deg1; rs = rs1; cvec = cvec1;
        outp = out1; n = n1;
        gid = (blockIdx.x - nb0) * 256 + threadIdx.x;
    }
    int node = gid >> 3;
    int lane = gid & 7;
    if (node >= n) return;
    int start = off[node];
    int d = deg[node];
    float acc[8];
#pragma unroll
    for (int i = 0; i < 8; i++) acc[i] = 0.0f;
    int j = 0;

    // pipelined 8-deep gather: gather batch k, prefetch indices k+1, accumulate k
    if (j + 8 <= d) {
        int sx[8];
#pragma unroll
        for (int k = 0; k < 8; k++) sx[k] = __ldg(&csr[start + j + k]);
        while (true) {
            uint4 xv[8];
#pragma unroll
            for (int k = 0; k < 8; k++)
                xv[k] = *reinterpret_cast<const uint4*>(h + (size_t)sx[k] * 64 + lane * 8);
            int nj = j + 8;
            bool more = (nj + 8 <= d);
            int sn[8];
            if (more) {
#pragma unroll
                for (int k = 0; k < 8; k++) sn[k] = __ldg(&csr[start + nj + k]);
            }
#pragma unroll
            for (int k = 0; k < 8; k++) acc_add8(acc, xv[k]);
            j = nj;
            if (!more) break;
#pragma unroll
            for (int k = 0; k < 8; k++) sx[k] = sn[k];
        }
    }
    if (j + 4 <= d) {
        int sx[4];
#pragma unroll
        for (int k = 0; k < 4; k++) sx[k] = __ldg(&csr[start + j + k]);
        uint4 xv[4];
#pragma unroll
        for (int k = 0; k < 4; k++)
            xv[k] = *reinterpret_cast<const uint4*>(h + (size_t)sx[k] * 64 + lane * 8);
#pragma unroll
        for (int k = 0; k < 4; k++) acc_add8(acc, xv[k]);
        j += 4;
    }
    for (; j < d; j++) {
        int s = __ldg(&csr[start + j]);
        uint4 x = *reinterpret_cast<const uint4*>(h + (size_t)s * 64 + lane * 8);
        acc_add8(acc, x);
    }

    float sc = rs[node];
    float cv[8];
    *reinterpret_cast<float4*>(&cv[0]) = *reinterpret_cast<const float4*>(cvec + lane * 8);
    *reinterpret_cast<float4*>(&cv[4]) = *reinterpret_cast<const float4*>(cvec + lane * 8 + 4);

    float v[8];
    if (NORM) {
#pragma unroll
        for (int i = 0; i < 8; i++) v[i] = fmaf(acc[i], sc, cv[i]);
        float ss = 0.0f;
#pragma unroll
        for (int i = 0; i < 8; i++) ss = fmaf(v[i], v[i], ss);
#pragma unroll
        for (int o = 4; o > 0; o >>= 1) ss += __shfl_xor_sync(0xFFFFFFFFu, ss, o, 8);
        float inv = 1.0f / fmaxf(sqrtf(ss), 1e-12f);
#pragma unroll
        for (int i = 0; i < 8; i++) v[i] *= inv;
    } else {
        float sc2 = sc * sc;
#pragma unroll
        for (int i = 0; i < 8; i++) v[i] = fmaf(acc[i], sc2, cv[i] * sc);
    }
    uint4 pk;
    __half2* hp = reinterpret_cast<__half2*>(&pk);
#pragma unroll
    for (int i = 0; i < 4; i++) hp[i] = __floats2half2_rn(v[2 * i], v[2 * i + 1]);
    *reinterpret_cast<uint4*>(outp + (size_t)node * 64 + lane * 8) = pk;
}

// ---------------- TF32 tensor-core GEMM: out = half( rs * (A@W + bias) ) ----------------
__device__ __forceinline__ uint32_t f2tf(float x) {
    uint32_t u;
    asm("cvt.rna.tf32.f32 %0, %1;" : "=r"(u) : "f"(x));
    return u;
}

#define MMA_TF32(c, a, bq)                                                     \
    asm volatile("mma.sync.aligned.m16n8k8.row.col.f32.tf32.tf32.f32 "        \
                 "{%0,%1,%2,%3}, {%4,%5,%6,%7}, {%8,%9}, {%0,%1,%2,%3};"      \
                 : "+f"(c[0]), "+f"(c[1]), "+f"(c[2]), "+f"(c[3])             \
                 : "r"(a[0]), "r"(a[1]), "r"(a[2]), "r"(a[3]),                \
                   "r"(bq[0]), "r"(bq[1]))

__global__ __launch_bounds__(256)
void mma_gemm64h_kernel(const float* __restrict__ A, const float* __restrict__ W,
                        const float* __restrict__ bias, const float* __restrict__ rs,
                        __half* __restrict__ C, int M, int K) {
    constexpr int BN = 64;
    constexpr int BM = 128, BK = 16;
    constexpr int WN = BN / 2;
    constexpr int NT = WN / 8;
    constexpr int ASTR = 20;
    constexpr int BSTR = BN + 8;
    __shared__ float As[2][BM * ASTR];
    __shared__ float Bs[2][BK * BSTR];

    const int tid = threadIdx.x;
    const int lane = tid & 31;
    const int warp = tid >> 5;
    const int wm = warp & 3;
    const int wn = warp >> 2;
    const int row0 = blockIdx.y * BM;

    const int arow = tid >> 1;
    const int akoff = (tid & 1) * 8;
    int garow = row0 + arow;
    if (garow > M - 1) garow = M - 1;
    const float* gA = A + (size_t)garow * K;

    constexpr int BQ = BN / 4;
    constexpr int NBC = (BK * BQ) / 256;

    float cacc[2][NT][4];
#pragma unroll
    for (int mt = 0; mt < 2; mt++)
#pragma unroll
        for (int nt = 0; nt < NT; nt++)
#pragma unroll
            for (int q = 0; q < 4; q++) cacc[mt][nt][q] = 0.0f;

    const int nsteps = K / BK;

#define ISSUE_TILE(s, k0)                                                          \
    {                                                                              \
        uint32_t da = (uint32_t)__cvta_generic_to_shared(                          \
            &As[s][arow * ASTR + akoff]);                                          \
        const float* sa = gA + (k0) + akoff;                                       \
        asm volatile("cp.async.ca.shared.global [%0], [%1], 16;" ::"r"(da),        \
                     "l"(sa));                                                     \
        asm volatile("cp.async.ca.shared.global [%0], [%1], 16;" ::"r"(da + 16),   \
                     "l"(sa + 4));                                                 \
        _Pragma("unroll") for (int i = 0; i < NBC; i++) {                          \
            int c = tid + i * 256;                                                 \
            int kr = c / BQ;                                                       \
            int n4 = (c % BQ) * 4;                                                 \
            uint32_t db = (uint32_t)__cvta_generic_to_shared(                      \
                &Bs[s][kr * BSTR + n4]);                                           \
            const float* sb = W + (size_t)((k0) + kr) * BN + n4;                   \
            asm volatile("cp.async.ca.shared.global [%0], [%1], 16;" ::"r"(db),    \
                         "l"(sb));                                                 \
        }                                                                          \
        asm volatile("cp.async.commit_group;");                                    \
    }

    ISSUE_TILE(0, 0);
    asm volatile("cp.async.wait_group 0;");
    __syncthreads();

    const int fr = lane >> 2;
    const int fk = lane & 3;
    const int fn = lane >> 2;

    for (int t = 0; t < nsteps; t++) {
        int s = t & 1;
        if (t + 1 < nsteps) {
            ISSUE_TILE(s ^ 1, (t + 1) * BK);
        }

#pragma unroll
        for (int kk = 0; kk < 2; kk++) {
            int kb = kk * 8;
            uint32_t af[2][4];
#pragma unroll
            for (int mt = 0; mt < 2; mt++) {
                int br = (wm * 32 + mt * 16);
                af[mt][0] = f2tf(As[s][(br + fr) * ASTR + kb + fk]);
                af[mt][1] = f2tf(As[s][(br + fr + 8) * ASTR + kb + fk]);
                af[mt][2] = f2tf(As[s][(br + fr) * ASTR + kb + fk + 4]);
                af[mt][3] = f2tf(As[s][(br + fr + 8) * ASTR + kb + fk + 4]);
            }
            uint32_t bf[NT][2];
#pragma unroll
            for (int nt = 0; nt < NT; nt++) {
                int n = wn * WN + nt * 8 + fn;
                bf[nt][0] = f2tf(Bs[s][(kb + fk) * BSTR + n]);
                bf[nt][1] = f2tf(Bs[s][(kb + fk + 4) * BSTR + n]);
            }
#pragma unroll
            for (int mt = 0; mt < 2; mt++)
#pragma unroll
                for (int nt = 0; nt < NT; nt++) MMA_TF32(cacc[mt][nt], af[mt], bf[nt]);
        }

        if (t + 1 < nsteps) {
            asm volatile("cp.async.wait_group 0;");
            __syncthreads();
        }
    }

#pragma unroll
    for (int mt = 0; mt < 2; mt++) {
        int r0 = row0 + wm * 32 + mt * 16 + fr;
        int r1 = r0 + 8;
        float s0 = (r0 < M) ? rs[r0] : 0.0f;
        float s1 = (r1 < M) ? rs[r1] : 0.0f;
#pragma unroll
        for (int nt = 0; nt < NT; nt++) {
            int cb = wn * WN + nt * 8 + (lane & 3) * 2;
            float2 bv = *reinterpret_cast<const float2*>(bias + cb);
            if (r0 < M) {
                __half2 hv = __floats2half2_rn((cacc[mt][nt][0] + bv.x) * s0,
                                               (cacc[mt][nt][1] + bv.y) * s0);
                *reinterpret_cast<__half2*>(C + (size_t)r0 * BN + cb) = hv;
            }
            if (r1 < M) {
                __half2 hv = __floats2half2_rn((cacc[mt][nt][2] + bv.x) * s1,
                                               (cacc[mt][nt][3] + bv.y) * s1);
                *reinterpret_cast<__half2*>(C + (size_t)r1 * BN + cb) = hv;
            }
        }
    }
#undef ISSUE_TILE
}

// ---------------- merged pair-dot (fp16 inputs), 2 lanes/pair, MLP 8 ----------------
__global__ __launch_bounds__(256)
void pairdot2_kernel(const __half* __restrict__ nu, const __half* __restrict__ nr,
                     const int* __restrict__ pos_u, const int* __restrict__ pos_r,
                     const int* __restrict__ neg_u, const int* __restrict__ neg_r,
                     float* __restrict__ out) {
    int gid = blockIdx.x * blockDim.x + threadIdx.x;
    int p = gid >> 1;
    int lane = gid & 1;
    if (p >= EP + EN) return;
    int u, r;
    if (p < EP) { u = __ldg(&pos_u[p]); r = __ldg(&pos_r[p]); }
    else        { u = __ldg(&neg_u[p - EP]); r = __ldg(&neg_r[p - EP]); }
    const __half* pa = nu + (size_t)u * 64 + lane * 32;
    const __half* pc = nr + (size_t)r * 64 + lane * 32;
    uint4 a[4], c[4];
#pragma unroll
    for (int k = 0; k < 4; k++) {
        a[k] = *reinterpret_cast<const uint4*>(pa + k * 8);
        c[k] = *reinterpret_cast<const uint4*>(pc + k * 8);
    }
    float d = 0.0f;
#pragma unroll
    for (int k = 0; k < 4; k++) {
        const __half2* a2 = reinterpret_cast<const __half2*>(&a[k]);
        const __half2* c2 = reinterpret_cast<const __half2*>(&c[k]);
#pragma unroll
        for (int i = 0; i < 4; i++) {
            float2 fa = __half22float2(a2[i]);
            float2 fc = __half22float2(c2[i]);
            d = fmaf(fa.x, fc.x, d);
            d = fmaf(fa.y, fc.y, d);
        }
    }
    d += __shfl_xor_sync(0xFFFFFFFFu, d, 1, 2);
    if (lane == 0) out[p] = d;
}

// ---------------- host launch ----------------
extern "C" void kernel_launch(void* const* d_in, const int* in_sizes, int n_in,
                              void* d_out, int out_size) {
    const float* user_feat = (const float*)d_in[0];
    const float* repo_feat = (const float*)d_in[1];
    const float* W_u   = (const float*)d_in[2];
    const float* b_u   = (const float*)d_in[3];
    const float* W_rp  = (const float*)d_in[4];
    const float* b_rp  = (const float*)d_in[5];
    const float* W1_ur = (const float*)d_in[6];
    const float* b1_ur = (const float*)d_in[7];
    const float* W1_ru = (const float*)d_in[8];
    const float* b1_ru = (const float*)d_in[9];
    const float* W2_ur = (const float*)d_in[10];
    const float* b2_ur = (const float*)d_in[11];
    const float* W2_ru = (const float*)d_in[12];
    const float* b2_ru = (const float*)d_in[13];
    const int* e_src = (const int*)d_in[14];
    const int* e_dst = (const int*)d_in[15];
    const int* pos_u = (const int*)d_in[16];
    const int* pos_r = (const int*)d_in[17];
    const int* neg_u = (const int*)d_in[18];
    const int* neg_r = (const int*)d_in[19];
    float* out = (float*)d_out;

    void* q[26];
    cudaGetSymbolAddress(&q[0],  g_spu);
    cudaGetSymbolAddress(&q[1],  g_spr);
    cudaGetSymbolAddress(&q[2],  g_st2_repo);
    cudaGetSymbolAddress(&q[3],  g_st2_user);
    cudaGetSymbolAddress(&q[4],  g_h2_user);
    cudaGetSymbolAddress(&q[5],  g_h2_repo);
    cudaGetSymbolAddress(&q[6],  g_deg_u);
    cudaGetSymbolAddress(&q[7],  g_deg_r);
    cudaGetSymbolAddress(&q[8],  g_rs_u);
    cudaGetSymbolAddress(&q[9],  g_rs_r);
    cudaGetSymbolAddress(&q[10], g_off_u);
    cudaGetSymbolAddress(&q[11], g_off_r);
    cudaGetSymbolAddress(&q[12], g_cur_u);
    cudaGetSymbolAddress(&q[13], g_cur_r);
    cudaGetSymbolAddress(&q[14], g_csr_u);
    cudaGetSymbolAddress(&q[15], g_csr_r);
    cudaGetSymbolAddress(&q[16], g_part_u);
    cudaGetSymbolAddress(&q[17], g_part_r);
    cudaGetSymbolAddress(&q[18], g_T2);
    cudaGetSymbolAddress(&q[19], g_Wfu2);
    cudaGetSymbolAddress(&q[20], g_Wfr);
    cudaGetSymbolAddress(&q[21], g_Wfpr);
    cudaGetSymbolAddress(&q[22], g_c0r);
    cudaGetSymbolAddress(&q[23], g_c0u);
    cudaGetSymbolAddress(&q[24], g_c1r);
    cudaGetSymbolAddress(&q[25], g_bfpr);

    __half* spu      = (__half*)q[0];
    __half* spr      = (__half*)q[1];
    __half* st2_repo = (__half*)q[2];
    __half* st2_user = (__half*)q[3];
    __half* h2_user  = (__half*)q[4];
    __half* h2_repo  = (__half*)q[5];
    int*    deg_u   = (int*)q[6];
    int*    deg_r   = (int*)q[7];
    float*  rs_u    = (float*)q[8];
    float*  rs_r    = (float*)q[9];
    int*    off_u   = (int*)q[10];
    int*    off_r   = (int*)q[11];
    int*    cur_u   = (int*)q[12];
    int*    cur_r   = (int*)q[13];
    int*    csr_u   = (int*)q[14];
    int*    csr_r   = (int*)q[15];
    int*    part_u  = (int*)q[16];
    int*    part_r  = (int*)q[17];
    float*  T2      = (float*)q[18];
    float*  Wfu2    = (float*)q[19];
    float*  Wfr     = (float*)q[20];
    float*  Wfpr    = (float*)q[21];
    float*  c0r     = (float*)q[22];
    float*  c0u     = (float*)q[23];
    float*  c1r     = (float*)q[24];
    float*  bfpr    = (float*)q[25];

    cudaStream_t s2 = g_hx.s2;

    // ===== fork side stream =====
    cudaEventRecord(g_hx.evFork, 0);
    cudaStreamWaitEvent(s2, g_hx.evFork, 0);

    // ---- side stream: weight/bias folds ----
    {
        FoldJobs ja;
        ja.A[0] = W1_ur; ja.B[0] = W2_ru; ja.C[0] = T2;   ja.M[0] = D0;
        ja.A[1] = W1_ru; ja.B[1] = W2_ur; ja.C[1] = Wfu2; ja.M[1] = D0;
        ja.A[2] = b1_ur; ja.B[2] = W2_ru; ja.C[2] = c0r;  ja.M[2] = 1;
        ja.A[3] = b1_ru; ja.B[3] = W2_ur; ja.C[3] = c0u;  ja.M[3] = 1;
        ja.boff[0] = 0; ja.boff[1] = 32; ja.boff[2] = 64; ja.boff[3] = 65; ja.boff[4] = 66;
        fold4_kernel<<<66, dim3(64, 4), 0, s2>>>(ja);

        FoldJobs jb;
        jb.A[0] = W_u;  jb.B[0] = T2;   jb.C[0] = Wfr;  jb.M[0] = IN_U;
        jb.A[1] = b_u;  jb.B[1] = T2;   jb.C[1] = c1r;  jb.M[1] = 1;
        jb.A[2] = W_rp; jb.B[2] = Wfu2; jb.C[2] = Wfpr; jb.M[2] = IN_R;
        jb.A[3] = b_rp; jb.B[3] = Wfu2; jb.C[3] = bfpr; jb.M[3] = 1;
        jb.boff[0] = 0; jb.boff[1] = 32; jb.boff[2] = 33; jb.boff[3] = 97; jb.boff[4] = 98;
        fold4_kernel<<<98, dim3(64, 4), 0, s2>>>(jb);
    }

    // ---- main stream: degrees only ----
    cudaMemsetAsync(deg_u, 0, NU * sizeof(int), 0);
    cudaMemsetAsync(deg_r, 0, NR * sizeof(int), 0);
    count_deg_kernel<<<(NE / 2 + 255) / 256, 256>>>(e_src, e_dst, deg_u, deg_r);
    cudaEventRecord(g_hx.evDeg, 0);

    // ---- side stream: rs + projections (need folds + degrees) ----
    cudaStreamWaitEvent(s2, g_hx.evDeg, 0);
    deg_to_rs2_kernel<<<(NU + NR + 255) / 256, 256, 0, s2>>>(deg_u, deg_r, rs_u, rs_r);
    {
        const int GYU = (NU + 127) / 128;
        const int GYR = (NR + 127) / 128;
        mma_gemm64h_kernel<<<dim3(1, GYU), 256, 0, s2>>>(user_feat, Wfr, c1r, rs_u, spu, NU, IN_U);
        mma_gemm64h_kernel<<<dim3(1, GYR), 256, 0, s2>>>(repo_feat, Wfpr, bfpr, rs_r, spr, NR, IN_R);
    }
    cudaEventRecord(g_hx.evGemm, s2);

    // ---- main stream (concurrent): CSR build ----
    scan_blocks2_kernel<<<NBU_C + NBR_C, 1024>>>(deg_u, deg_r, off_u, off_r, part_u, part_r);
    scan_partials2_kernel<<<2, 128>>>(part_u, part_r);
    scan_add2_kernel<<<NBU_C + NBR_C, 1024>>>(off_u, off_r, part_u, part_r, cur_u, cur_r);
    fill_csr_kernel<<<(NE + 255) / 256, 256>>>(e_src, e_dst, cur_u, cur_r, csr_u, csr_r, NE);

    // ===== join =====
    cudaStreamWaitEvent(0, g_hx.evGemm, 0);

    // ---- layer-1 dual aggregation ----
    {
        int nb0 = (NR * 8 + 255) / 256;
        int nb1 = (NU * 8 + 255) / 256;
        agg64dual_kernel<false><<<nb0 + nb1, 256>>>(
            spu, csr_r, off_r, deg_r, rs_r, c0r, st2_repo, NR, nb0,
            spr, csr_u, off_u, deg_u, rs_u, c0u, st2_user, NU);
    }

    // ---- layer-2 dual aggregation with fused bias + L2norm ----
    {
        int nb0 = (NR * 8 + 255) / 256;
        int nb1 = (NU * 8 + 255) / 256;
        agg64dual_kernel<true><<<nb0 + nb1, 256>>>(
            st2_user, csr_r, off_r, deg_r, rs_r, b2_ur, h2_repo, NR, nb0,
            st2_repo, csr_u, off_u, deg_u, rs_u, b2_ru, h2_user, NU);
    }

    // ---- merged pair dots (2 lanes/pair) ----
    pairdot2_kernel<<<((EP + EN) * 2 + 255) / 256, 256>>>(h2_user, h2_repo,
                                                          pos_u, pos_r, neg_u, neg_r, out);
}

// round 11
// speedup vs baseline: 1.0398x; 1.0398x over previous
#include <cuda_runtime.h>
#include <cuda_fp16.h>
#include <math.h>
#include <stdint.h>

// ---------------- problem constants ----------------
#define NU 100000
#define NR 50000
#define NE 1000000
#define EP 500000
#define EN 500000
#define IN_U 128
#define IN_R 256
#define D0 128
#define DH 128
#define DOUT 64

#define NBU_C 98   // ceil(NU/1024)
#define NBR_C 49   // ceil(NR/1024)

// ---------------- static scratch ----------------
__device__ __half g_spu[(size_t)NU * DOUT];
__device__ __half g_spr[(size_t)NR * DOUT];
__device__ __half g_st2_repo[(size_t)NR * DOUT];
__device__ __half g_st2_user[(size_t)NU * DOUT];
__device__ __half g_h2_user[(size_t)NU * DOUT];
__device__ __half g_h2_repo[(size_t)NR * DOUT];
__device__ int   g_deg_u[NU];
__device__ int   g_deg_r[NR];
__device__ int   g_off_u[NU];
__device__ int   g_off_r[NR];
__device__ int   g_cur_u[NU];
__device__ int   g_cur_r[NR];
__device__ int   g_csr_u[NE];
__device__ int   g_csr_r[NE];
__device__ int   g_part_u[256];
__device__ int   g_part_r[256];
// folded weights / biases
__device__ float g_T2[D0 * DOUT];
__device__ float g_Wfu2[DH * DOUT];
__device__ float g_Wfr[IN_U * DOUT];
__device__ float g_Wfpr[IN_R * DOUT];
__device__ float g_c0r[DOUT];
__device__ float g_c0u[DOUT];
__device__ float g_c1r[DOUT];
__device__ float g_bfpr[DOUT];

// ---------------- stream/event context (static-init; no device mem APIs) ----------------
struct HxStreams {
    cudaStream_t s2;
    cudaEvent_t evFork, evDeg, evGemm;
    HxStreams() {
        cudaStreamCreateWithFlags(&s2, cudaStreamNonBlocking);
        cudaEventCreateWithFlags(&evFork, cudaEventDisableTiming);
        cudaEventCreateWithFlags(&evDeg, cudaEventDisableTiming);
        cudaEventCreateWithFlags(&evGemm, cudaEventDisableTiming);
    }
};
static HxStreams g_hx;

__device__ __forceinline__ float deg_rs(int d) {
    return rsqrtf((float)(d > 1 ? d : 1));
}

// ---------------- degree count (2 edges per thread) ----------------
__global__ void count_deg_kernel(const int* __restrict__ e_src,
                                 const int* __restrict__ e_dst,
                                 int* __restrict__ deg_u,
                                 int* __restrict__ deg_r) {
    int i = (blockIdx.x * blockDim.x + threadIdx.x) * 2;
    if (i + 1 < NE) {
        int2 s2v = *reinterpret_cast<const int2*>(e_src + i);
        int2 d2v = *reinterpret_cast<const int2*>(e_dst + i);
        atomicAdd(&deg_u[s2v.x], 1);
        atomicAdd(&deg_u[s2v.y], 1);
        atomicAdd(&deg_r[d2v.x], 1);
        atomicAdd(&deg_r[d2v.y], 1);
    } else if (i < NE) {
        atomicAdd(&deg_u[e_src[i]], 1);
        atomicAdd(&deg_r[e_dst[i]], 1);
    }
}

// ---------------- batched exclusive scans (warp-shuffle) ----------------
__global__ void scan_blocks2_kernel(const int* __restrict__ deg_u, const int* __restrict__ deg_r,
                                    int* __restrict__ off_u, int* __restrict__ off_r,
                                    int* __restrict__ part_u, int* __restrict__ part_r) {
    __shared__ int wsum[32];
    int b = blockIdx.x;
    const int* in;
    int* out;
    int* partials;
    int n, lb;
    if (b < NBU_C) { in = deg_u; out = off_u; partials = part_u; n = NU; lb = b; }
    else           { in = deg_r; out = off_r; partials = part_r; n = NR; lb = b - NBU_C; }
    int tid = threadIdx.x;
    int lane = tid & 31;
    int wid = tid >> 5;
    int gid = lb * 1024 + tid;
    int v = (gid < n) ? in[gid] : 0;

    int x = v;
#pragma unroll
    for (int o = 1; o < 32; o <<= 1) {
        int t = __shfl_up_sync(0xFFFFFFFFu, x, o);
        if (lane >= o) x += t;
    }
    if (lane == 31) wsum[wid] = x;
    __syncthreads();
    if (wid == 0) {
        int w = wsum[lane];
        int y = w;
#pragma unroll
        for (int o = 1; o < 32; o <<= 1) {
            int t = __shfl_up_sync(0xFFFFFFFFu, y, o);
            if (lane >= o) y += t;
        }
        wsum[lane] = y - w;   // exclusive warp offsets
    }
    __syncthreads();
    int incl = x + wsum[wid];
    if (gid < n) out[gid] = incl - v;   // exclusive
    if (tid == 1023) partials[lb] = incl;
}

__global__ void scan_partials2_kernel(int* __restrict__ part_u, int* __restrict__ part_r) {
    __shared__ int s[128];
    int* partials = (blockIdx.x == 0) ? part_u : part_r;
    int nb = (blockIdx.x == 0) ? NBU_C : NBR_C;
    int tid = threadIdx.x;
    int v = (tid < nb) ? partials[tid] : 0;
    s[tid] = v;
    __syncthreads();
#pragma unroll
    for (int o = 1; o < 128; o <<= 1) {
        int t = (tid >= o) ? s[tid - o] : 0;
        __syncthreads();
        s[tid] += t;
        __syncthreads();
    }
    if (tid < nb) partials[tid] = s[tid] - v;
}

__global__ void scan_add2_kernel(int* __restrict__ off_u, int* __restrict__ off_r,
                                 const int* __restrict__ part_u, const int* __restrict__ part_r,
                                 int* __restrict__ cur_u, int* __restrict__ cur_r) {
    int b = blockIdx.x;
    int* out;
    int* cur;
    const int* partials;
    int n, lb;
    if (b < NBU_C) { out = off_u; cur = cur_u; partials = part_u; n = NU; lb = b; }
    else           { out = off_r; cur = cur_r; partials = part_r; n = NR; lb = b - NBU_C; }
    int gid = lb * 1024 + threadIdx.x;
    if (gid < n) {
        int v = out[gid] + partials[lb];
        out[gid] = v;
        cur[gid] = v;
    }
}

// ---------------- CSR fill ----------------
__global__ void fill_csr_kernel(const int* __restrict__ e_src, const int* __restrict__ e_dst,
                                int* __restrict__ cur_u, int* __restrict__ cur_r,
                                int* __restrict__ csr_u, int* __restrict__ csr_r, int E) {
    int i = blockIdx.x * blockDim.x + threadIdx.x;
    if (i < E) {
        int s = e_src[i];
        int d = e_dst[i];
        int pr = atomicAdd(&cur_r[d], 1);
        csr_r[pr] = s;
        int pu = atomicAdd(&cur_u[s], 1);
        csr_u[pu] = d;
    }
}

// ---------------- batched fold: up to 4 jobs of C[M,64] = A[M,128] @ B[128,64] ----------------
struct FoldJobs {
    const float* A[4];
    const float* B[4];
    float* C[4];
    int M[4];
    int boff[5];
};

__global__ void fold4_kernel(FoldJobs jobs) {
    int bx = blockIdx.x;
    int j = 0;
    while (j < 3 && bx >= jobs.boff[j + 1]) j++;
    const float* A = jobs.A[j];
    const float* B = jobs.B[j];
    float* C = jobs.C[j];
    int M = jobs.M[j];
    int m0 = (bx - jobs.boff[j]) * 4;

    __shared__ float sA[4][128];
    int tx = threadIdx.x;
    int ty = threadIdx.y;
    int tid = ty * 64 + tx;
    for (int i = tid; i < 4 * 128; i += 256) {
        int r = i >> 7, k = i & 127;
        sA[r][k] = (m0 + r < M) ? A[(size_t)(m0 + r) * 128 + k] : 0.0f;
    }
    __syncthreads();
    int m = m0 + ty;
    if (m >= M) return;
    float acc0 = 0.f, acc1 = 0.f;
#pragma unroll
    for (int k = 0; k < 128; k += 2) {
        acc0 = fmaf(sA[ty][k], B[k * 64 + tx], acc0);
        acc1 = fmaf(sA[ty][k + 1], B[(k + 1) * 64 + tx], acc1);
    }
    C[(size_t)m * 64 + tx] = acc0 + acc1;
}

// ---------------- fp16 helpers ----------------
__device__ __forceinline__ void acc_add8(float* acc, uint4 x) {
    const __half2* p = reinterpret_cast<const __half2*>(&x);
#pragma unroll
    for (int i = 0; i < 4; i++) {
        float2 f = __half22float2(p[i]);
        acc[2 * i] += f.x;
        acc[2 * i + 1] += f.y;
    }
}

// ---------------- dual-job 64-wide fp16 CSR aggregation, fused epilogues ----------------
// sources PRE-SCALED by rs_src. 8 lanes/node, plain 8-deep gather (round-9 form).
// rs computed inline from deg (already loaded).
template <bool NORM>
__global__ __launch_bounds__(256)
void agg64dual_kernel(const __half* __restrict__ h0, const int* __restrict__ csr0,
                      const int* __restrict__ off0, const int* __restrict__ deg0,
                      const float* __restrict__ cvec0,
                      __half* __restrict__ out0, int n0, int nb0,
                      const __half* __restrict__ h1, const int* __restrict__ csr1,
                      const int* __restrict__ off1, const int* __restrict__ deg1,
                      const float* __restrict__ cvec1,
                      __half* __restrict__ out1, int n1) {
    const __half* h;
    const int *csr, *off, *deg;
    const float *cvec;
    __half* outp;
    int n, gid;
    if ((int)blockIdx.x < nb0) {
        h = h0; csr = csr0; off = off0; deg = deg0; cvec = cvec0;
        outp = out0; n = n0;
        gid = blockIdx.x * 256 + threadIdx.x;
    } else {
        h = h1; csr = csr1; off = off1; deg = deg1; cvec = cvec1;
        outp = out1; n = n1;
        gid = (blockIdx.x - nb0) * 256 + threadIdx.x;
    }
    int node = gid >> 3;
    int lane = gid & 7;
    if (node >= n) return;
    int start = off[node];
    int d = deg[node];
    float acc[8];
#pragma unroll
    for (int i = 0; i < 8; i++) acc[i] = 0.0f;
    int j = 0;
    // 8-deep gather: 8 outstanding 16B loads per thread
    for (; j + 8 <= d; j += 8) {
        int sx[8];
#pragma unroll
        for (int k = 0; k < 8; k++) sx[k] = __ldg(&csr[start + j + k]);
        uint4 xv[8];
#pragma unroll
        for (int k = 0; k < 8; k++)
            xv[k] = *reinterpret_cast<const uint4*>(h + (size_t)sx[k] * 64 + lane * 8);
#pragma unroll
        for (int k = 0; k < 8; k++) acc_add8(acc, xv[k]);
    }
    for (; j + 4 <= d; j += 4) {
        int sx[4];
#pragma unroll
        for (int k = 0; k < 4; k++) sx[k] = __ldg(&csr[start + j + k]);
        uint4 xv[4];
#pragma unroll
        for (int k = 0; k < 4; k++)
            xv[k] = *reinterpret_cast<const uint4*>(h + (size_t)sx[k] * 64 + lane * 8);
#pragma unroll
        for (int k = 0; k < 4; k++) acc_add8(acc, xv[k]);
    }
    for (; j < d; j++) {
        int s = __ldg(&csr[start + j]);
        uint4 x = *reinterpret_cast<const uint4*>(h + (size_t)s * 64 + lane * 8);
        acc_add8(acc, x);
    }

    float sc = deg_rs(d);
    float cv[8];
    *reinterpret_cast<float4*>(&cv[0]) = *reinterpret_cast<const float4*>(cvec + lane * 8);
    *reinterpret_cast<float4*>(&cv[4]) = *reinterpret_cast<const float4*>(cvec + lane * 8 + 4);

    float v[8];
    if (NORM) {
#pragma unroll
        for (int i = 0; i < 8; i++) v[i] = fmaf(acc[i], sc, cv[i]);
        float ss = 0.0f;
#pragma unroll
        for (int i = 0; i < 8; i++) ss = fmaf(v[i], v[i], ss);
#pragma unroll
        for (int o = 4; o > 0; o >>= 1) ss += __shfl_xor_sync(0xFFFFFFFFu, ss, o, 8);
        float inv = 1.0f / fmaxf(sqrtf(ss), 1e-12f);
#pragma unroll
        for (int i = 0; i < 8; i++) v[i] *= inv;
    } else {
        float sc2 = sc * sc;
#pragma unroll
        for (int i = 0; i < 8; i++) v[i] = fmaf(acc[i], sc2, cv[i] * sc);
    }
    uint4 pk;
    __half2* hp = reinterpret_cast<__half2*>(&pk);
#pragma unroll
    for (int i = 0; i < 4; i++) hp[i] = __floats2half2_rn(v[2 * i], v[2 * i + 1]);
    *reinterpret_cast<uint4*>(outp + (size_t)node * 64 + lane * 8) = pk;
}

// ---------------- TF32 tensor-core GEMM: out = half( rs(deg) * (A@W + bias) ) ----------------
__device__ __forceinline__ uint32_t f2tf(float x) {
    uint32_t u;
    asm("cvt.rna.tf32.f32 %0, %1;" : "=r"(u) : "f"(x));
    return u;
}

#define MMA_TF32(c, a, bq)                                                     \
    asm volatile("mma.sync.aligned.m16n8k8.row.col.f32.tf32.tf32.f32 "        \
                 "{%0,%1,%2,%3}, {%4,%5,%6,%7}, {%8,%9}, {%0,%1,%2,%3};"      \
                 : "+f"(c[0]), "+f"(c[1]), "+f"(c[2]), "+f"(c[3])             \
                 : "r"(a[0]), "r"(a[1]), "r"(a[2]), "r"(a[3]),                \
                   "r"(bq[0]), "r"(bq[1]))

__global__ __launch_bounds__(256)
void mma_gemm64h_kernel(const float* __restrict__ A, const float* __restrict__ W,
                        const float* __restrict__ bias, const int* __restrict__ deg,
                        __half* __restrict__ C, int M, int K) {
    constexpr int BN = 64;
    constexpr int BM = 128, BK = 16;
    constexpr int WN = BN / 2;
    constexpr int NT = WN / 8;
    constexpr int ASTR = 20;
    constexpr int BSTR = BN + 8;
    __shared__ float As[2][BM * ASTR];
    __shared__ float Bs[2][BK * BSTR];

    const int tid = threadIdx.x;
    const int lane = tid & 31;
    const int warp = tid >> 5;
    const int wm = warp & 3;
    const int wn = warp >> 2;
    const int row0 = blockIdx.y * BM;

    const int arow = tid >> 1;
    const int akoff = (tid & 1) * 8;
    int garow = row0 + arow;
    if (garow > M - 1) garow = M - 1;
    const float* gA = A + (size_t)garow * K;

    constexpr int BQ = BN / 4;
    constexpr int NBC = (BK * BQ) / 256;

    float cacc[2][NT][4];
#pragma unroll
    for (int mt = 0; mt < 2; mt++)
#pragma unroll
        for (int nt = 0; nt < NT; nt++)
#pragma unroll
            for (int q = 0; q < 4; q++) cacc[mt][nt][q] = 0.0f;

    const int nsteps = K / BK;

#define ISSUE_TILE(s, k0)                                                          \
    {                                                                              \
        uint32_t da = (uint32_t)__cvta_generic_to_shared(                          \
            &As[s][arow * ASTR + akoff]);                                          \
        const float* sa = gA + (k0) + akoff;                                       \
        asm volatile("cp.async.ca.shared.global [%0], [%1], 16;" ::"r"(da),        \
                     "l"(sa));                                                     \
        asm volatile("cp.async.ca.shared.global [%0], [%1], 16;" ::"r"(da + 16),   \
                     "l"(sa + 4));                                                 \
        _Pragma("unroll") for (int i = 0; i < NBC; i++) {                          \
            int c = tid + i * 256;                                                 \
            int kr = c / BQ;                                                       \
            int n4 = (c % BQ) * 4;                                                 \
            uint32_t db = (uint32_t)__cvta_generic_to_shared(                      \
                &Bs[s][kr * BSTR + n4]);                                           \
            const float* sb = W + (size_t)((k0) + kr) * BN + n4;                   \
            asm volatile("cp.async.ca.shared.global [%0], [%1], 16;" ::"r"(db),    \
                         "l"(sb));                                                 \
        }                                                                          \
        asm volatile("cp.async.commit_group;");                                    \
    }

    ISSUE_TILE(0, 0);
    asm volatile("cp.async.wait_group 0;");
    __syncthreads();

    const int fr = lane >> 2;
    const int fk = lane & 3;
    const int fn = lane >> 2;

    for (int t = 0; t < nsteps; t++) {
        int s = t & 1;
        if (t + 1 < nsteps) {
            ISSUE_TILE(s ^ 1, (t + 1) * BK);
        }

#pragma unroll
        for (int kk = 0; kk < 2; kk++) {
            int kb = kk * 8;
            uint32_t af[2][4];
#pragma unroll
            for (int mt = 0; mt < 2; mt++) {
                int br = (wm * 32 + mt * 16);
                af[mt][0] = f2tf(As[s][(br + fr) * ASTR + kb + fk]);
                af[mt][1] = f2tf(As[s][(br + fr + 8) * ASTR + kb + fk]);
                af[mt][2] = f2tf(As[s][(br + fr) * ASTR + kb + fk + 4]);
                af[mt][3] = f2tf(As[s][(br + fr + 8) * ASTR + kb + fk + 4]);
            }
            uint32_t bf[NT][2];
#pragma unroll
            for (int nt = 0; nt < NT; nt++) {
                int n = wn * WN + nt * 8 + fn;
                bf[nt][0] = f2tf(Bs[s][(kb + fk) * BSTR + n]);
                bf[nt][1] = f2tf(Bs[s][(kb + fk + 4) * BSTR + n]);
            }
#pragma unroll
            for (int mt = 0; mt < 2; mt++)
#pragma unroll
                for (int nt = 0; nt < NT; nt++) MMA_TF32(cacc[mt][nt], af[mt], bf[nt]);
        }

        if (t + 1 < nsteps) {
            asm volatile("cp.async.wait_group 0;");
            __syncthreads();
        }
    }

#pragma unroll
    for (int mt = 0; mt < 2; mt++) {
        int r0 = row0 + wm * 32 + mt * 16 + fr;
        int r1 = r0 + 8;
        float s0 = (r0 < M) ? deg_rs(deg[r0]) : 0.0f;
        float s1 = (r1 < M) ? deg_rs(deg[r1]) : 0.0f;
#pragma unroll
        for (int nt = 0; nt < NT; nt++) {
            int cb = wn * WN + nt * 8 + (lane & 3) * 2;
            float2 bv = *reinterpret_cast<const float2*>(bias + cb);
            if (r0 < M) {
                __half2 hv = __floats2half2_rn((cacc[mt][nt][0] + bv.x) * s0,
                                               (cacc[mt][nt][1] + bv.y) * s0);
                *reinterpret_cast<__half2*>(C + (size_t)r0 * BN + cb) = hv;
            }
            if (r1 < M) {
                __half2 hv = __floats2half2_rn((cacc[mt][nt][2] + bv.x) * s1,
                                               (cacc[mt][nt][3] + bv.y) * s1);
                *reinterpret_cast<__half2*>(C + (size_t)r1 * BN + cb) = hv;
            }
        }
    }
#undef ISSUE_TILE
}

// ---------------- merged pair-dot (fp16 inputs), 4 lanes/pair (round-9 form) ----------------
__global__ __launch_bounds__(256)
void pairdot2_kernel(const __half* __restrict__ nu, const __half* __restrict__ nr,
                     const int* __restrict__ pos_u, const int* __restrict__ pos_r,
                     const int* __restrict__ neg_u, const int* __restrict__ neg_r,
                     float* __restrict__ out) {
    int gid = blockIdx.x * blockDim.x + threadIdx.x;
    int p = gid >> 2;
    int lane = gid & 3;
    if (p >= EP + EN) return;
    int u, r;
    if (p < EP) { u = __ldg(&pos_u[p]); r = __ldg(&pos_r[p]); }
    else        { u = __ldg(&neg_u[p - EP]); r = __ldg(&neg_r[p - EP]); }
    const __half* pa = nu + (size_t)u * 64 + lane * 16;
    const __half* pc = nr + (size_t)r * 64 + lane * 16;
    uint4 a0 = *reinterpret_cast<const uint4*>(pa);
    uint4 a1 = *reinterpret_cast<const uint4*>(pa + 8);
    uint4 c0 = *reinterpret_cast<const uint4*>(pc);
    uint4 c1 = *reinterpret_cast<const uint4*>(pc + 8);
    const __half2* a2 = reinterpret_cast<const __half2*>(&a0);
    const __half2* a3 = reinterpret_cast<const __half2*>(&a1);
    const __half2* c2 = reinterpret_cast<const __half2*>(&c0);
    const __half2* c3 = reinterpret_cast<const __half2*>(&c1);
    float d = 0.0f;
#pragma unroll
    for (int i = 0; i < 4; i++) {
        float2 fa = __half22float2(a2[i]);
        float2 fc = __half22float2(c2[i]);
        d = fmaf(fa.x, fc.x, d);
        d = fmaf(fa.y, fc.y, d);
    }
#pragma unroll
    for (int i = 0; i < 4; i++) {
        float2 fa = __half22float2(a3[i]);
        float2 fc = __half22float2(c3[i]);
        d = fmaf(fa.x, fc.x, d);
        d = fmaf(fa.y, fc.y, d);
    }
#pragma unroll
    for (int o = 2; o > 0; o >>= 1) d += __shfl_xor_sync(0xFFFFFFFFu, d, o, 4);
    if (lane == 0) out[p] = d;
}

// ---------------- host launch ----------------
extern "C" void kernel_launch(void* const* d_in, const int* in_sizes, int n_in,
                              void* d_out, int out_size) {
    const float* user_feat = (const float*)d_in[0];
    const float* repo_feat = (const float*)d_in[1];
    const float* W_u   = (const float*)d_in[2];
    const float* b_u   = (const float*)d_in[3];
    const float* W_rp  = (const float*)d_in[4];
    const float* b_rp  = (const float*)d_in[5];
    const float* W1_ur = (const float*)d_in[6];
    const float* b1_ur = (const float*)d_in[7];
    const float* W1_ru = (const float*)d_in[8];
    const float* b1_ru = (const float*)d_in[9];
    const float* W2_ur = (const float*)d_in[10];
    const float* b2_ur = (const float*)d_in[11];
    const float* W2_ru = (const float*)d_in[12];
    const float* b2_ru = (const float*)d_in[13];
    const int* e_src = (const int*)d_in[14];
    const int* e_dst = (const int*)d_in[15];
    const int* pos_u = (const int*)d_in[16];
    const int* pos_r = (const int*)d_in[17];
    const int* neg_u = (const int*)d_in[18];
    const int* neg_r = (const int*)d_in[19];
    float* out = (float*)d_out;

    void* q[24];
    cudaGetSymbolAddress(&q[0],  g_spu);
    cudaGetSymbolAddress(&q[1],  g_spr);
    cudaGetSymbolAddress(&q[2],  g_st2_repo);
    cudaGetSymbolAddress(&q[3],  g_st2_user);
    cudaGetSymbolAddress(&q[4],  g_h2_user);
    cudaGetSymbolAddress(&q[5],  g_h2_repo);
    cudaGetSymbolAddress(&q[6],  g_deg_u);
    cudaGetSymbolAddress(&q[7],  g_deg_r);
    cudaGetSymbolAddress(&q[8],  g_off_u);
    cudaGetSymbolAddress(&q[9],  g_off_r);
    cudaGetSymbolAddress(&q[10], g_cur_u);
    cudaGetSymbolAddress(&q[11], g_cur_r);
    cudaGetSymbolAddress(&q[12], g_csr_u);
    cudaGetSymbolAddress(&q[13], g_csr_r);
    cudaGetSymbolAddress(&q[14], g_part_u);
    cudaGetSymbolAddress(&q[15], g_part_r);
    cudaGetSymbolAddress(&q[16], g_T2);
    cudaGetSymbolAddress(&q[17], g_Wfu2);
    cudaGetSymbolAddress(&q[18], g_Wfr);
    cudaGetSymbolAddress(&q[19], g_Wfpr);
    cudaGetSymbolAddress(&q[20], g_c0r);
    cudaGetSymbolAddress(&q[21], g_c0u);
    cudaGetSymbolAddress(&q[22], g_c1r);
    cudaGetSymbolAddress(&q[23], g_bfpr);

    __half* spu      = (__half*)q[0];
    __half* spr      = (__half*)q[1];
    __half* st2_repo = (__half*)q[2];
    __half* st2_user = (__half*)q[3];
    __half* h2_user  = (__half*)q[4];
    __half* h2_repo  = (__half*)q[5];
    int*    deg_u   = (int*)q[6];
    int*    deg_r   = (int*)q[7];
    int*    off_u   = (int*)q[8];
    int*    off_r   = (int*)q[9];
    int*    cur_u   = (int*)q[10];
    int*    cur_r   = (int*)q[11];
    int*    csr_u   = (int*)q[12];
    int*    csr_r   = (int*)q[13];
    int*    part_u  = (int*)q[14];
    int*    part_r  = (int*)q[15];
    float*  T2      = (float*)q[16];
    float*  Wfu2    = (float*)q[17];
    float*  Wfr     = (float*)q[18];
    float*  Wfpr    = (float*)q[19];
    float*  c0r     = (float*)q[20];
    float*  c0u     = (float*)q[21];
    float*  c1r     = (float*)q[22];
    float*  bfpr    = (float*)q[23];

    cudaStream_t s2 = g_hx.s2;

    // ===== fork side stream =====
    cudaEventRecord(g_hx.evFork, 0);
    cudaStreamWaitEvent(s2, g_hx.evFork, 0);

    // ---- side stream: weight/bias folds ----
    {
        FoldJobs ja;
        ja.A[0] = W1_ur; ja.B[0] = W2_ru; ja.C[0] = T2;   ja.M[0] = D0;
        ja.A[1] = W1_ru; ja.B[1] = W2_ur; ja.C[1] = Wfu2; ja.M[1] = D0;
        ja.A[2] = b1_ur; ja.B[2] = W2_ru; ja.C[2] = c0r;  ja.M[2] = 1;
        ja.A[3] = b1_ru; ja.B[3] = W2_ur; ja.C[3] = c0u;  ja.M[3] = 1;
        ja.boff[0] = 0; ja.boff[1] = 32; ja.boff[2] = 64; ja.boff[3] = 65; ja.boff[4] = 66;
        fold4_kernel<<<66, dim3(64, 4), 0, s2>>>(ja);

        FoldJobs jb;
        jb.A[0] = W_u;  jb.B[0] = T2;   jb.C[0] = Wfr;  jb.M[0] = IN_U;
        jb.A[1] = b_u;  jb.B[1] = T2;   jb.C[1] = c1r;  jb.M[1] = 1;
        jb.A[2] = W_rp; jb.B[2] = Wfu2; jb.C[2] = Wfpr; jb.M[2] = IN_R;
        jb.A[3] = b_rp; jb.B[3] = Wfu2; jb.C[3] = bfpr; jb.M[3] = 1;
        jb.boff[0] = 0; jb.boff[1] = 32; jb.boff[2] = 33; jb.boff[3] = 97; jb.boff[4] = 98;
        fold4_kernel<<<98, dim3(64, 4), 0, s2>>>(jb);
    }

    // ---- main stream: degrees only ----
    cudaMemsetAsync(deg_u, 0, NU * sizeof(int), 0);
    cudaMemsetAsync(deg_r, 0, NR * sizeof(int), 0);
    count_deg_kernel<<<(NE / 2 + 255) / 256, 256>>>(e_src, e_dst, deg_u, deg_r);
    cudaEventRecord(g_hx.evDeg, 0);

    // ---- side stream: projections (need folds + degrees; rs inlined from deg) ----
    cudaStreamWaitEvent(s2, g_hx.evDeg, 0);
    {
        const int GYU = (NU + 127) / 128;
        const int GYR = (NR + 127) / 128;
        mma_gemm64h_kernel<<<dim3(1, GYU), 256, 0, s2>>>(user_feat, Wfr, c1r, deg_u, spu, NU, IN_U);
        mma_gemm64h_kernel<<<dim3(1, GYR), 256, 0, s2>>>(repo_feat, Wfpr, bfpr, deg_r, spr, NR, IN_R);
    }
    cudaEventRecord(g_hx.evGemm, s2);

    // ---- main stream (concurrent): CSR build ----
    scan_blocks2_kernel<<<NBU_C + NBR_C, 1024>>>(deg_u, deg_r, off_u, off_r, part_u, part_r);
    scan_partials2_kernel<<<2, 128>>>(part_u, part_r);
    scan_add2_kernel<<<NBU_C + NBR_C, 1024>>>(off_u, off_r, part_u, part_r, cur_u, cur_r);
    fill_csr_kernel<<<(NE + 255) / 256, 256>>>(e_src, e_dst, cur_u, cur_r, csr_u, csr_r, NE);

    // ===== join =====
    cudaStreamWaitEvent(0, g_hx.evGemm, 0);

    // ---- layer-1 dual aggregation ----
    {
        int nb0 = (NR * 8 + 255) / 256;
        int nb1 = (NU * 8 + 255) / 256;
        agg64dual_kernel<false><<<nb0 + nb1, 256>>>(
            spu, csr_r, off_r, deg_r, c0r, st2_repo, NR, nb0,
            spr, csr_u, off_u, deg_u, c0u, st2_user, NU);
    }

    // ---- layer-2 dual aggregation with fused bias + L2norm ----
    {
        int nb0 = (NR * 8 + 255) / 256;
        int nb1 = (NU * 8 + 255) / 256;
        agg64dual_kernel<true><<<nb0 + nb1, 256>>>(
            st2_user, csr_r, off_r, deg_r, b2_ur, h2_repo, NR, nb0,
            st2_repo, csr_u, off_u, deg_u, b2_ru, h2_user, NU);
    }

    // ---- merged pair dots (4 lanes/pair) ----
    pairdot2_kernel<<<((EP + EN) * 4 + 255) / 256, 256>>>(h2_user, h2_repo,
                                                          pos_u, pos_r, neg_u, neg_r, out);
}

// round 12
// speedup vs baseline: 1.1074x; 1.0649x over previous
#include <cuda_runtime.h>
#include <cuda_fp16.h>
#include <math.h>
#include <stdint.h>

// ---------------- problem constants ----------------
#define NU 100000
#define NR 50000
#define NE 1000000
#define EP 500000
#define EN 500000
#define IN_U 128
#define IN_R 256
#define D0 128
#define DH 128
#define DOUT 64

#define NBU_C 98   // ceil(NU/1024)
#define NBR_C 49   // ceil(NR/1024)
#define GYU_C 782  // ceil(NU/128)
#define GYR_C 391  // ceil(NR/128)

// ---------------- static scratch ----------------
__device__ __half g_spu[(size_t)NU * DOUT];
__device__ __half g_spr[(size_t)NR * DOUT];
__device__ __half g_st2_repo[(size_t)NR * DOUT];
__device__ __half g_st2_user[(size_t)NU * DOUT];
__device__ __half g_h2_user[(size_t)NU * DOUT];
__device__ __half g_h2_repo[(size_t)NR * DOUT];
__device__ int   g_deg_u[NU];
__device__ int   g_deg_r[NR];
__device__ int   g_off_u[NU];
__device__ int   g_off_r[NR];
__device__ int   g_cur_u[NU];
__device__ int   g_cur_r[NR];
__device__ int   g_csr_u[NE];
__device__ int   g_csr_r[NE];
__device__ int   g_part_u[256];
__device__ int   g_part_r[256];
// folded weights / biases
__device__ float g_T2[D0 * DOUT];
__device__ float g_Wfu2[DH * DOUT];
__device__ float g_Wfr[IN_U * DOUT];
__device__ float g_Wfpr[IN_R * DOUT];
__device__ float g_c0r[DOUT];
__device__ float g_c0u[DOUT];
__device__ float g_c1r[DOUT];
__device__ float g_bfpr[DOUT];

// ---------------- stream/event context (static-init; no device mem APIs) ----------------
struct HxStreams {
    cudaStream_t s2;
    cudaEvent_t evFork, evDeg, evGemm;
    HxStreams() {
        cudaStreamCreateWithFlags(&s2, cudaStreamNonBlocking);
        cudaEventCreateWithFlags(&evFork, cudaEventDisableTiming);
        cudaEventCreateWithFlags(&evDeg, cudaEventDisableTiming);
        cudaEventCreateWithFlags(&evGemm, cudaEventDisableTiming);
    }
};
static HxStreams g_hx;

__device__ __forceinline__ float deg_rs(int d) {
    return rsqrtf((float)(d > 1 ? d : 1));
}

// ---------------- degree count (2 edges per thread) ----------------
__global__ void count_deg_kernel(const int* __restrict__ e_src,
                                 const int* __restrict__ e_dst,
                                 int* __restrict__ deg_u,
                                 int* __restrict__ deg_r) {
    int i = (blockIdx.x * blockDim.x + threadIdx.x) * 2;
    if (i + 1 < NE) {
        int2 s2v = *reinterpret_cast<const int2*>(e_src + i);
        int2 d2v = *reinterpret_cast<const int2*>(e_dst + i);
        atomicAdd(&deg_u[s2v.x], 1);
        atomicAdd(&deg_u[s2v.y], 1);
        atomicAdd(&deg_r[d2v.x], 1);
        atomicAdd(&deg_r[d2v.y], 1);
    } else if (i < NE) {
        atomicAdd(&deg_u[e_src[i]], 1);
        atomicAdd(&deg_r[e_dst[i]], 1);
    }
}

// ---------------- batched exclusive scans (warp-shuffle) ----------------
__global__ void scan_blocks2_kernel(const int* __restrict__ deg_u, const int* __restrict__ deg_r,
                                    int* __restrict__ off_u, int* __restrict__ off_r,
                                    int* __restrict__ part_u, int* __restrict__ part_r) {
    __shared__ int wsum[32];
    int b = blockIdx.x;
    const int* in;
    int* out;
    int* partials;
    int n, lb;
    if (b < NBU_C) { in = deg_u; out = off_u; partials = part_u; n = NU; lb = b; }
    else           { in = deg_r; out = off_r; partials = part_r; n = NR; lb = b - NBU_C; }
    int tid = threadIdx.x;
    int lane = tid & 31;
    int wid = tid >> 5;
    int gid = lb * 1024 + tid;
    int v = (gid < n) ? in[gid] : 0;

    int x = v;
#pragma unroll
    for (int o = 1; o < 32; o <<= 1) {
        int t = __shfl_up_sync(0xFFFFFFFFu, x, o);
        if (lane >= o) x += t;
    }
    if (lane == 31) wsum[wid] = x;
    __syncthreads();
    if (wid == 0) {
        int w = wsum[lane];
        int y = w;
#pragma unroll
        for (int o = 1; o < 32; o <<= 1) {
            int t = __shfl_up_sync(0xFFFFFFFFu, y, o);
            if (lane >= o) y += t;
        }
        wsum[lane] = y - w;
    }
    __syncthreads();
    int incl = x + wsum[wid];
    if (gid < n) out[gid] = incl - v;
    if (tid == 1023) partials[lb] = incl;
}

__global__ void scan_partials2_kernel(int* __restrict__ part_u, int* __restrict__ part_r) {
    __shared__ int s[128];
    int* partials = (blockIdx.x == 0) ? part_u : part_r;
    int nb = (blockIdx.x == 0) ? NBU_C : NBR_C;
    int tid = threadIdx.x;
    int v = (tid < nb) ? partials[tid] : 0;
    s[tid] = v;
    __syncthreads();
#pragma unroll
    for (int o = 1; o < 128; o <<= 1) {
        int t = (tid >= o) ? s[tid - o] : 0;
        __syncthreads();
        s[tid] += t;
        __syncthreads();
    }
    if (tid < nb) partials[tid] = s[tid] - v;
}

__global__ void scan_add2_kernel(int* __restrict__ off_u, int* __restrict__ off_r,
                                 const int* __restrict__ part_u, const int* __restrict__ part_r,
                                 int* __restrict__ cur_u, int* __restrict__ cur_r) {
    int b = blockIdx.x;
    int* out;
    int* cur;
    const int* partials;
    int n, lb;
    if (b < NBU_C) { out = off_u; cur = cur_u; partials = part_u; n = NU; lb = b; }
    else           { out = off_r; cur = cur_r; partials = part_r; n = NR; lb = b - NBU_C; }
    int gid = lb * 1024 + threadIdx.x;
    if (gid < n) {
        int v = out[gid] + partials[lb];
        out[gid] = v;
        cur[gid] = v;
    }
}

// ---------------- CSR fill ----------------
__global__ void fill_csr_kernel(const int* __restrict__ e_src, const int* __restrict__ e_dst,
                                int* __restrict__ cur_u, int* __restrict__ cur_r,
                                int* __restrict__ csr_u, int* __restrict__ csr_r, int E) {
    int i = blockIdx.x * blockDim.x + threadIdx.x;
    if (i < E) {
        int s = e_src[i];
        int d = e_dst[i];
        int pr = atomicAdd(&cur_r[d], 1);
        csr_r[pr] = s;
        int pu = atomicAdd(&cur_u[s], 1);
        csr_u[pu] = d;
    }
}

// ---------------- batched fold: up to 4 jobs of C[M,64] = A[M,128] @ B[128,64] ----------------
struct FoldJobs {
    const float* A[4];
    const float* B[4];
    float* C[4];
    int M[4];
    int boff[5];
};

__global__ void fold4_kernel(FoldJobs jobs) {
    int bx = blockIdx.x;
    int j = 0;
    while (j < 3 && bx >= jobs.boff[j + 1]) j++;
    const float* A = jobs.A[j];
    const float* B = jobs.B[j];
    float* C = jobs.C[j];
    int M = jobs.M[j];
    int m0 = (bx - jobs.boff[j]) * 4;

    __shared__ float sA[4][128];
    int tx = threadIdx.x;
    int ty = threadIdx.y;
    int tid = ty * 64 + tx;
    for (int i = tid; i < 4 * 128; i += 256) {
        int r = i >> 7, k = i & 127;
        sA[r][k] = (m0 + r < M) ? A[(size_t)(m0 + r) * 128 + k] : 0.0f;
    }
    __syncthreads();
    int m = m0 + ty;
    if (m >= M) return;
    float acc0 = 0.f, acc1 = 0.f;
#pragma unroll
    for (int k = 0; k < 128; k += 2) {
        acc0 = fmaf(sA[ty][k], B[k * 64 + tx], acc0);
        acc1 = fmaf(sA[ty][k + 1], B[(k + 1) * 64 + tx], acc1);
    }
    C[(size_t)m * 64 + tx] = acc0 + acc1;
}

// ---------------- fp16 helpers ----------------
__device__ __forceinline__ void acc_add8(float* acc, uint4 x) {
    const __half2* p = reinterpret_cast<const __half2*>(&x);
#pragma unroll
    for (int i = 0; i < 4; i++) {
        float2 f = __half22float2(p[i]);
        acc[2 * i] += f.x;
        acc[2 * i + 1] += f.y;
    }
}

// ---------------- dual-job 64-wide fp16 CSR aggregation, fused epilogues ----------------
template <bool NORM>
__global__ __launch_bounds__(256)
void agg64dual_kernel(const __half* __restrict__ h0, const int* __restrict__ csr0,
                      const int* __restrict__ off0, const int* __restrict__ deg0,
                      const float* __restrict__ cvec0,
                      __half* __restrict__ out0, int n0, int nb0,
                      const __half* __restrict__ h1, const int* __restrict__ csr1,
                      const int* __restrict__ off1, const int* __restrict__ deg1,
                      const float* __restrict__ cvec1,
                      __half* __restrict__ out1, int n1) {
    const __half* h;
    const int *csr, *off, *deg;
    const float *cvec;
    __half* outp;
    int n, gid;
    if ((int)blockIdx.x < nb0) {
        h = h0; csr = csr0; off = off0; deg = deg0; cvec = cvec0;
        outp = out0; n = n0;
        gid = blockIdx.x * 256 + threadIdx.x;
    } else {
        h = h1; csr = csr1; off = off1; deg = deg1; cvec = cvec1;
        outp = out1; n = n1;
        gid = (blockIdx.x - nb0) * 256 + threadIdx.x;
    }
    int node = gid >> 3;
    int lane = gid & 7;
    if (node >= n) return;
    int start = off[node];
    int d = deg[node];
    float acc[8];
#pragma unroll
    for (int i = 0; i < 8; i++) acc[i] = 0.0f;
    int j = 0;
    for (; j + 8 <= d; j += 8) {
        int sx[8];
#pragma unroll
        for (int k = 0; k < 8; k++) sx[k] = __ldg(&csr[start + j + k]);
        uint4 xv[8];
#pragma unroll
        for (int k = 0; k < 8; k++)
            xv[k] = *reinterpret_cast<const uint4*>(h + (size_t)sx[k] * 64 + lane * 8);
#pragma unroll
        for (int k = 0; k < 8; k++) acc_add8(acc, xv[k]);
    }
    for (; j + 4 <= d; j += 4) {
        int sx[4];
#pragma unroll
        for (int k = 0; k < 4; k++) sx[k] = __ldg(&csr[start + j + k]);
        uint4 xv[4];
#pragma unroll
        for (int k = 0; k < 4; k++)
            xv[k] = *reinterpret_cast<const uint4*>(h + (size_t)sx[k] * 64 + lane * 8);
#pragma unroll
        for (int k = 0; k < 4; k++) acc_add8(acc, xv[k]);
    }
    for (; j < d; j++) {
        int s = __ldg(&csr[start + j]);
        uint4 x = *reinterpret_cast<const uint4*>(h + (size_t)s * 64 + lane * 8);
        acc_add8(acc, x);
    }

    float sc = deg_rs(d);
    float cv[8];
    *reinterpret_cast<float4*>(&cv[0]) = *reinterpret_cast<const float4*>(cvec + lane * 8);
    *reinterpret_cast<float4*>(&cv[4]) = *reinterpret_cast<const float4*>(cvec + lane * 8 + 4);

    float v[8];
    if (NORM) {
#pragma unroll
        for (int i = 0; i < 8; i++) v[i] = fmaf(acc[i], sc, cv[i]);
        float ss = 0.0f;
#pragma unroll
        for (int i = 0; i < 8; i++) ss = fmaf(v[i], v[i], ss);
#pragma unroll
        for (int o = 4; o > 0; o >>= 1) ss += __shfl_xor_sync(0xFFFFFFFFu, ss, o, 8);
        float inv = 1.0f / fmaxf(sqrtf(ss), 1e-12f);
#pragma unroll
        for (int i = 0; i < 8; i++) v[i] *= inv;
    } else {
        float sc2 = sc * sc;
#pragma unroll
        for (int i = 0; i < 8; i++) v[i] = fmaf(acc[i], sc2, cv[i] * sc);
    }
    uint4 pk;
    __half2* hp = reinterpret_cast<__half2*>(&pk);
#pragma unroll
    for (int i = 0; i < 4; i++) hp[i] = __floats2half2_rn(v[2 * i], v[2 * i + 1]);
    *reinterpret_cast<uint4*>(outp + (size_t)node * 64 + lane * 8) = pk;
}

// ---------------- TF32 tensor-core GEMM, dual-job, 3-stage pipeline ----------------
// out = half( rs(deg) * (A@W + bias) ); two jobs dispatched by blockIdx.y range.
__device__ __forceinline__ uint32_t f2tf(float x) {
    uint32_t u;
    asm("cvt.rna.tf32.f32 %0, %1;" : "=r"(u) : "f"(x));
    return u;
}

#define MMA_TF32(c, a, bq)                                                     \
    asm volatile("mma.sync.aligned.m16n8k8.row.col.f32.tf32.tf32.f32 "        \
                 "{%0,%1,%2,%3}, {%4,%5,%6,%7}, {%8,%9}, {%0,%1,%2,%3};"      \
                 : "+f"(c[0]), "+f"(c[1]), "+f"(c[2]), "+f"(c[3])             \
                 : "r"(a[0]), "r"(a[1]), "r"(a[2]), "r"(a[3]),                \
                   "r"(bq[0]), "r"(bq[1]))

__global__ __launch_bounds__(256)
void mma_gemm64h_dual_kernel(
    const float* __restrict__ A0, const float* __restrict__ W0,
    const float* __restrict__ bias0, const int* __restrict__ deg0,
    __half* __restrict__ C0, int M0, int K0, int nby0,
    const float* __restrict__ A1, const float* __restrict__ W1,
    const float* __restrict__ bias1, const int* __restrict__ deg1,
    __half* __restrict__ C1, int M1, int K1) {
    constexpr int BN = 64;
    constexpr int BM = 128, BK = 16;
    constexpr int WN = BN / 2;      // 32
    constexpr int NT = WN / 8;      // 4
    constexpr int ASTR = 20;
    constexpr int BSTR = BN + 8;    // 72
    constexpr int STAGES = 3;
    __shared__ float As[STAGES][BM * ASTR];
    __shared__ float Bs[STAGES][BK * BSTR];

    const float *A, *W, *bias;
    const int* deg;
    __half* C;
    int M, K, by;
    if ((int)blockIdx.y < nby0) {
        A = A0; W = W0; bias = bias0; deg = deg0; C = C0; M = M0; K = K0;
        by = blockIdx.y;
    } else {
        A = A1; W = W1; bias = bias1; deg = deg1; C = C1; M = M1; K = K1;
        by = blockIdx.y - nby0;
    }

    const int tid = threadIdx.x;
    const int lane = tid & 31;
    const int warp = tid >> 5;
    const int wm = warp & 3;
    const int wn = warp >> 2;
    const int row0 = by * BM;

    const int arow = tid >> 1;
    const int akoff = (tid & 1) * 8;
    int garow = row0 + arow;
    if (garow > M - 1) garow = M - 1;
    const float* gA = A + (size_t)garow * K;

    // B tile: 16 rows x 64 cols = 256 float4 chunks -> 1 per thread
    const int wkr = tid >> 4;            // 0..15 (k row)
    const int wn4 = (tid & 15) * 4;      // 0..60

    float cacc[2][NT][4];
#pragma unroll
    for (int mt = 0; mt < 2; mt++)
#pragma unroll
        for (int nt = 0; nt < NT; nt++)
#pragma unroll
            for (int q = 0; q < 4; q++) cacc[mt][nt][q] = 0.0f;

    const int nsteps = K / BK;   // 8 or 16

#define ISSUE_TILE(s, k0)                                                          \
    {                                                                              \
        uint32_t da = (uint32_t)__cvta_generic_to_shared(                          \
            &As[s][arow * ASTR + akoff]);                                          \
        const float* sa = gA + (k0) + akoff;                                       \
        asm volatile("cp.async.ca.shared.global [%0], [%1], 16;" ::"r"(da),        \
                     "l"(sa));                                                     \
        asm volatile("cp.async.ca.shared.global [%0], [%1], 16;" ::"r"(da + 16),   \
                     "l"(sa + 4));                                                 \
        uint32_t db = (uint32_t)__cvta_generic_to_shared(                          \
            &Bs[s][wkr * BSTR + wn4]);                                             \
        const float* sb = W + (size_t)((k0) + wkr) * BN + wn4;                     \
        asm volatile("cp.async.ca.shared.global [%0], [%1], 16;" ::"r"(db),        \
                     "l"(sb));                                                     \
        asm volatile("cp.async.commit_group;");                                    \
    }

    // prologue: 2 tiles in flight, wait for tile 0
    ISSUE_TILE(0, 0);
    ISSUE_TILE(1, BK);
    asm volatile("cp.async.wait_group 1;");
    __syncthreads();

    const int fr = lane >> 2;
    const int fk = lane & 3;
    const int fn = lane >> 2;

    for (int t = 0; t < nsteps; t++) {
        int s = t % STAGES;
        if (t + 2 < nsteps) {
            int sn = (t + 2) % STAGES;
            ISSUE_TILE(sn, (t + 2) * BK);
        }

#pragma unroll
        for (int kk = 0; kk < 2; kk++) {
            int kb = kk * 8;
            uint32_t af[2][4];
#pragma unroll
            for (int mt = 0; mt < 2; mt++) {
                int br = (wm * 32 + mt * 16);
                af[mt][0] = f2tf(As[s][(br + fr) * ASTR + kb + fk]);
                af[mt][1] = f2tf(As[s][(br + fr + 8) * ASTR + kb + fk]);
                af[mt][2] = f2tf(As[s][(br + fr) * ASTR + kb + fk + 4]);
                af[mt][3] = f2tf(As[s][(br + fr + 8) * ASTR + kb + fk + 4]);
            }
            uint32_t bf[NT][2];
#pragma unroll
            for (int nt = 0; nt < NT; nt++) {
                int n = wn * WN + nt * 8 + fn;
                bf[nt][0] = f2tf(Bs[s][(kb + fk) * BSTR + n]);
                bf[nt][1] = f2tf(Bs[s][(kb + fk + 4) * BSTR + n]);
            }
#pragma unroll
            for (int mt = 0; mt < 2; mt++)
#pragma unroll
                for (int nt = 0; nt < NT; nt++) MMA_TF32(cacc[mt][nt], af[mt], bf[nt]);
        }

        // ensure tile t+1 ready for next iteration; keep tile t+2 in flight
        if (t + 2 < nsteps) {
            asm volatile("cp.async.wait_group 1;");
            __syncthreads();
        } else if (t + 1 < nsteps) {
            asm volatile("cp.async.wait_group 0;");
            __syncthreads();
        }
    }

#pragma unroll
    for (int mt = 0; mt < 2; mt++) {
        int r0 = row0 + wm * 32 + mt * 16 + fr;
        int r1 = r0 + 8;
        float s0 = (r0 < M) ? deg_rs(deg[r0]) : 0.0f;
        float s1 = (r1 < M) ? deg_rs(deg[r1]) : 0.0f;
#pragma unroll
        for (int nt = 0; nt < NT; nt++) {
            int cb = wn * WN + nt * 8 + (lane & 3) * 2;
            float2 bv = *reinterpret_cast<const float2*>(bias + cb);
            if (r0 < M) {
                __half2 hv = __floats2half2_rn((cacc[mt][nt][0] + bv.x) * s0,
                                               (cacc[mt][nt][1] + bv.y) * s0);
                *reinterpret_cast<__half2*>(C + (size_t)r0 * BN + cb) = hv;
            }
            if (r1 < M) {
                __half2 hv = __floats2half2_rn((cacc[mt][nt][2] + bv.x) * s1,
                                               (cacc[mt][nt][3] + bv.y) * s1);
                *reinterpret_cast<__half2*>(C + (size_t)r1 * BN + cb) = hv;
            }
        }
    }
#undef ISSUE_TILE
}

// ---------------- merged pair-dot (fp16 inputs), 4 lanes/pair ----------------
__global__ __launch_bounds__(256)
void pairdot2_kernel(const __half* __restrict__ nu, const __half* __restrict__ nr,
                     const int* __restrict__ pos_u, const int* __restrict__ pos_r,
                     const int* __restrict__ neg_u, const int* __restrict__ neg_r,
                     float* __restrict__ out) {
    int gid = blockIdx.x * blockDim.x + threadIdx.x;
    int p = gid >> 2;
    int lane = gid & 3;
    if (p >= EP + EN) return;
    int u, r;
    if (p < EP) { u = __ldg(&pos_u[p]); r = __ldg(&pos_r[p]); }
    else        { u = __ldg(&neg_u[p - EP]); r = __ldg(&neg_r[p - EP]); }
    const __half* pa = nu + (size_t)u * 64 + lane * 16;
    const __half* pc = nr + (size_t)r * 64 + lane * 16;
    uint4 a0 = *reinterpret_cast<const uint4*>(pa);
    uint4 a1 = *reinterpret_cast<const uint4*>(pa + 8);
    uint4 c0 = *reinterpret_cast<const uint4*>(pc);
    uint4 c1 = *reinterpret_cast<const uint4*>(pc + 8);
    const __half2* a2 = reinterpret_cast<const __half2*>(&a0);
    const __half2* a3 = reinterpret_cast<const __half2*>(&a1);
    const __half2* c2 = reinterpret_cast<const __half2*>(&c0);
    const __half2* c3 = reinterpret_cast<const __half2*>(&c1);
    float d = 0.0f;
#pragma unroll
    for (int i = 0; i < 4; i++) {
        float2 fa = __half22float2(a2[i]);
        float2 fc = __half22float2(c2[i]);
        d = fmaf(fa.x, fc.x, d);
        d = fmaf(fa.y, fc.y, d);
    }
#pragma unroll
    for (int i = 0; i < 4; i++) {
        float2 fa = __half22float2(a3[i]);
        float2 fc = __half22float2(c3[i]);
        d = fmaf(fa.x, fc.x, d);
        d = fmaf(fa.y, fc.y, d);
    }
#pragma unroll
    for (int o = 2; o > 0; o >>= 1) d += __shfl_xor_sync(0xFFFFFFFFu, d, o, 4);
    if (lane == 0) out[p] = d;
}

// ---------------- host launch ----------------
extern "C" void kernel_launch(void* const* d_in, const int* in_sizes, int n_in,
                              void* d_out, int out_size) {
    const float* user_feat = (const float*)d_in[0];
    const float* repo_feat = (const float*)d_in[1];
    const float* W_u   = (const float*)d_in[2];
    const float* b_u   = (const float*)d_in[3];
    const float* W_rp  = (const float*)d_in[4];
    const float* b_rp  = (const float*)d_in[5];
    const float* W1_ur = (const float*)d_in[6];
    const float* b1_ur = (const float*)d_in[7];
    const float* W1_ru = (const float*)d_in[8];
    const float* b1_ru = (const float*)d_in[9];
    const float* W2_ur = (const float*)d_in[10];
    const float* b2_ur = (const float*)d_in[11];
    const float* W2_ru = (const float*)d_in[12];
    const float* b2_ru = (const float*)d_in[13];
    const int* e_src = (const int*)d_in[14];
    const int* e_dst = (const int*)d_in[15];
    const int* pos_u = (const int*)d_in[16];
    const int* pos_r = (const int*)d_in[17];
    const int* neg_u = (const int*)d_in[18];
    const int* neg_r = (const int*)d_in[19];
    float* out = (float*)d_out;

    void* q[24];
    cudaGetSymbolAddress(&q[0],  g_spu);
    cudaGetSymbolAddress(&q[1],  g_spr);
    cudaGetSymbolAddress(&q[2],  g_st2_repo);
    cudaGetSymbolAddress(&q[3],  g_st2_user);
    cudaGetSymbolAddress(&q[4],  g_h2_user);
    cudaGetSymbolAddress(&q[5],  g_h2_repo);
    cudaGetSymbolAddress(&q[6],  g_deg_u);
    cudaGetSymbolAddress(&q[7],  g_deg_r);
    cudaGetSymbolAddress(&q[8],  g_off_u);
    cudaGetSymbolAddress(&q[9],  g_off_r);
    cudaGetSymbolAddress(&q[10], g_cur_u);
    cudaGetSymbolAddress(&q[11], g_cur_r);
    cudaGetSymbolAddress(&q[12], g_csr_u);
    cudaGetSymbolAddress(&q[13], g_csr_r);
    cudaGetSymbolAddress(&q[14], g_part_u);
    cudaGetSymbolAddress(&q[15], g_part_r);
    cudaGetSymbolAddress(&q[16], g_T2);
    cudaGetSymbolAddress(&q[17], g_Wfu2);
    cudaGetSymbolAddress(&q[18], g_Wfr);
    cudaGetSymbolAddress(&q[19], g_Wfpr);
    cudaGetSymbolAddress(&q[20], g_c0r);
    cudaGetSymbolAddress(&q[21], g_c0u);
    cudaGetSymbolAddress(&q[22], g_c1r);
    cudaGetSymbolAddress(&q[23], g_bfpr);

    __half* spu      = (__half*)q[0];
    __half* spr      = (__half*)q[1];
    __half* st2_repo = (__half*)q[2];
    __half* st2_user = (__half*)q[3];
    __half* h2_user  = (__half*)q[4];
    __half* h2_repo  = (__half*)q[5];
    int*    deg_u   = (int*)q[6];
    int*    deg_r   = (int*)q[7];
    int*    off_u   = (int*)q[8];
    int*    off_r   = (int*)q[9];
    int*    cur_u   = (int*)q[10];
    int*    cur_r   = (int*)q[11];
    int*    csr_u   = (int*)q[12];
    int*    csr_r   = (int*)q[13];
    int*    part_u  = (int*)q[14];
    int*    part_r  = (int*)q[15];
    float*  T2      = (float*)q[16];
    float*  Wfu2    = (float*)q[17];
    float*  Wfr     = (float*)q[18];
    float*  Wfpr    = (float*)q[19];
    float*  c0r     = (float*)q[20];
    float*  c0u     = (float*)q[21];
    float*  c1r     = (float*)q[22];
    float*  bfpr    = (float*)q[23];

    cudaStream_t s2 = g_hx.s2;

    // ===== fork side stream =====
    cudaEventRecord(g_hx.evFork, 0);
    cudaStreamWaitEvent(s2, g_hx.evFork, 0);

    // ---- side stream: weight/bias folds ----
    {
        FoldJobs ja;
        ja.A[0] = W1_ur; ja.B[0] = W2_ru; ja.C[0] = T2;   ja.M[0] = D0;
        ja.A[1] = W1_ru; ja.B[1] = W2_ur; ja.C[1] = Wfu2; ja.M[1] = D0;
        ja.A[2] = b1_ur; ja.B[2] = W2_ru; ja.C[2] = c0r;  ja.M[2] = 1;
        ja.A[3] = b1_ru; ja.B[3] = W2_ur; ja.C[3] = c0u;  ja.M[3] = 1;
        ja.boff[0] = 0; ja.boff[1] = 32; ja.boff[2] = 64; ja.boff[3] = 65; ja.boff[4] = 66;
        fold4_kernel<<<66, dim3(64, 4), 0, s2>>>(ja);

        FoldJobs jb;
        jb.A[0] = W_u;  jb.B[0] = T2;   jb.C[0] = Wfr;  jb.M[0] = IN_U;
        jb.A[1] = b_u;  jb.B[1] = T2;   jb.C[1] = c1r;  jb.M[1] = 1;
        jb.A[2] = W_rp; jb.B[2] = Wfu2; jb.C[2] = Wfpr; jb.M[2] = IN_R;
        jb.A[3] = b_rp; jb.B[3] = Wfu2; jb.C[3] = bfpr; jb.M[3] = 1;
        jb.boff[0] = 0; jb.boff[1] = 32; jb.boff[2] = 33; jb.boff[3] = 97; jb.boff[4] = 98;
        fold4_kernel<<<98, dim3(64, 4), 0, s2>>>(jb);
    }

    // ---- main stream: degrees only ----
    cudaMemsetAsync(deg_u, 0, NU * sizeof(int), 0);
    cudaMemsetAsync(deg_r, 0, NR * sizeof(int), 0);
    count_deg_kernel<<<(NE / 2 + 255) / 256, 256>>>(e_src, e_dst, deg_u, deg_r);
    cudaEventRecord(g_hx.evDeg, 0);

    // ---- side stream: merged projections (single launch; rs inlined from deg) ----
    cudaStreamWaitEvent(s2, g_hx.evDeg, 0);
    mma_gemm64h_dual_kernel<<<dim3(1, GYU_C + GYR_C), 256, 0, s2>>>(
        user_feat, Wfr, c1r, deg_u, spu, NU, IN_U, GYU_C,
        repo_feat, Wfpr, bfpr, deg_r, spr, NR, IN_R);
    cudaEventRecord(g_hx.evGemm, s2);

    // ---- main stream (concurrent): CSR build ----
    scan_blocks2_kernel<<<NBU_C + NBR_C, 1024>>>(deg_u, deg_r, off_u, off_r, part_u, part_r);
    scan_partials2_kernel<<<2, 128>>>(part_u, part_r);
    scan_add2_kernel<<<NBU_C + NBR_C, 1024>>>(off_u, off_r, part_u, part_r, cur_u, cur_r);
    fill_csr_kernel<<<(NE + 255) / 256, 256>>>(e_src, e_dst, cur_u, cur_r, csr_u, csr_r, NE);

    // ===== join =====
    cudaStreamWaitEvent(0, g_hx.evGemm, 0);

    // ---- layer-1 dual aggregation ----
    {
        int nb0 = (NR * 8 + 255) / 256;
        int nb1 = (NU * 8 + 255) / 256;
        agg64dual_kernel<false><<<nb0 + nb1, 256>>>(
            spu, csr_r, off_r, deg_r, c0r, st2_repo, NR, nb0,
            spr, csr_u, off_u, deg_u, c0u, st2_user, NU);
    }

    // ---- layer-2 dual aggregation with fused bias + L2norm ----
    {
        int nb0 = (NR * 8 + 255) / 256;
        int nb1 = (NU * 8 + 255) / 256;
        agg64dual_kernel<true><<<nb0 + nb1, 256>>>(
            st2_user, csr_r, off_r, deg_r, b2_ur, h2_repo, NR, nb0,
            st2_repo, csr_u, off_u, deg_u, b2_ru, h2_user, NU);
    }

    // ---- merged pair dots (4 lanes/pair) ----
    pairdot2_kernel<<<((EP + EN) * 4 + 255) / 256, 256>>>(h2_user, h2_repo,
                                                          pos_u, pos_r, neg_u, neg_r, out);
}

// round 13
// speedup vs baseline: 1.1113x; 1.0036x over previous
#include <cuda_runtime.h>
#include <cuda_fp16.h>
#include <math.h>
#include <stdint.h>

// ---------------- problem constants ----------------
#define NU 100000
#define NR 50000
#define NE 1000000
#define EP 500000
#define EN 500000
#define IN_U 128
#define IN_R 256
#define D0 128
#define DH 128
#define DOUT 64

#define NBU_C 98   // ceil(NU/1024)
#define NBR_C 49   // ceil(NR/1024)
#define GYU_C 782  // ceil(NU/128)
#define GYR_C 391  // ceil(NR/128)

// ---------------- static scratch ----------------
__device__ __half g_spu[(size_t)NU * DOUT];
__device__ __half g_spr[(size_t)NR * DOUT];
__device__ __half g_st2_repo[(size_t)NR * DOUT];
__device__ __half g_st2_user[(size_t)NU * DOUT];
__device__ __half g_h2_user[(size_t)NU * DOUT];
__device__ __half g_h2_repo[(size_t)NR * DOUT];
__device__ int   g_deg_u[NU];
__device__ int   g_deg_r[NR];
__device__ int   g_off_u[NU];
__device__ int   g_off_r[NR];
__device__ int   g_cur_u[NU];
__device__ int   g_cur_r[NR];
__device__ int   g_csr_u[NE];
__device__ int   g_csr_r[NE];
__device__ int   g_part_u[256];
__device__ int   g_part_r[256];
// folded weights / biases
__device__ float g_T2[D0 * DOUT];
__device__ float g_Wfu2[DH * DOUT];
__device__ float g_Wfr[IN_U * DOUT];   // tf32-pre-rounded
__device__ float g_Wfpr[IN_R * DOUT];  // tf32-pre-rounded
__device__ float g_c0r[DOUT];
__device__ float g_c0u[DOUT];
__device__ float g_c1r[DOUT];
__device__ float g_bfpr[DOUT];

// ---------------- stream/event context ----------------
struct HxStreams {
    cudaStream_t s2;
    cudaEvent_t evFork, evDeg, evGemm;
    HxStreams() {
        cudaStreamCreateWithFlags(&s2, cudaStreamNonBlocking);
        cudaEventCreateWithFlags(&evFork, cudaEventDisableTiming);
        cudaEventCreateWithFlags(&evDeg, cudaEventDisableTiming);
        cudaEventCreateWithFlags(&evGemm, cudaEventDisableTiming);
    }
};
static HxStreams g_hx;

__device__ __forceinline__ float deg_rs(int d) {
    return rsqrtf((float)(d > 1 ? d : 1));
}

__device__ __forceinline__ uint32_t f2tf(float x) {
    uint32_t u;
    asm("cvt.rna.tf32.f32 %0, %1;" : "=r"(u) : "f"(x));
    return u;
}

// ---------------- degree count (2 edges per thread) ----------------
__global__ void count_deg_kernel(const int* __restrict__ e_src,
                                 const int* __restrict__ e_dst,
                                 int* __restrict__ deg_u,
                                 int* __restrict__ deg_r) {
    int i = (blockIdx.x * blockDim.x + threadIdx.x) * 2;
    if (i + 1 < NE) {
        int2 s2v = *reinterpret_cast<const int2*>(e_src + i);
        int2 d2v = *reinterpret_cast<const int2*>(e_dst + i);
        atomicAdd(&deg_u[s2v.x], 1);
        atomicAdd(&deg_u[s2v.y], 1);
        atomicAdd(&deg_r[d2v.x], 1);
        atomicAdd(&deg_r[d2v.y], 1);
    } else if (i < NE) {
        atomicAdd(&deg_u[e_src[i]], 1);
        atomicAdd(&deg_r[e_dst[i]], 1);
    }
}

// ---------------- batched exclusive scans (warp-shuffle) ----------------
__global__ void scan_blocks2_kernel(const int* __restrict__ deg_u, const int* __restrict__ deg_r,
                                    int* __restrict__ off_u, int* __restrict__ off_r,
                                    int* __restrict__ part_u, int* __restrict__ part_r) {
    __shared__ int wsum[32];
    int b = blockIdx.x;
    const int* in;
    int* out;
    int* partials;
    int n, lb;
    if (b < NBU_C) { in = deg_u; out = off_u; partials = part_u; n = NU; lb = b; }
    else           { in = deg_r; out = off_r; partials = part_r; n = NR; lb = b - NBU_C; }
    int tid = threadIdx.x;
    int lane = tid & 31;
    int wid = tid >> 5;
    int gid = lb * 1024 + tid;
    int v = (gid < n) ? in[gid] : 0;

    int x = v;
#pragma unroll
    for (int o = 1; o < 32; o <<= 1) {
        int t = __shfl_up_sync(0xFFFFFFFFu, x, o);
        if (lane >= o) x += t;
    }
    if (lane == 31) wsum[wid] = x;
    __syncthreads();
    if (wid == 0) {
        int w = wsum[lane];
        int y = w;
#pragma unroll
        for (int o = 1; o < 32; o <<= 1) {
            int t = __shfl_up_sync(0xFFFFFFFFu, y, o);
            if (lane >= o) y += t;
        }
        wsum[lane] = y - w;
    }
    __syncthreads();
    int incl = x + wsum[wid];
    if (gid < n) out[gid] = incl - v;
    if (tid == 1023) partials[lb] = incl;
}

__global__ void scan_partials2_kernel(int* __restrict__ part_u, int* __restrict__ part_r) {
    __shared__ int s[128];
    int* partials = (blockIdx.x == 0) ? part_u : part_r;
    int nb = (blockIdx.x == 0) ? NBU_C : NBR_C;
    int tid = threadIdx.x;
    int v = (tid < nb) ? partials[tid] : 0;
    s[tid] = v;
    __syncthreads();
#pragma unroll
    for (int o = 1; o < 128; o <<= 1) {
        int t = (tid >= o) ? s[tid - o] : 0;
        __syncthreads();
        s[tid] += t;
        __syncthreads();
    }
    if (tid < nb) partials[tid] = s[tid] - v;
}

__global__ void scan_add2_kernel(int* __restrict__ off_u, int* __restrict__ off_r,
                                 const int* __restrict__ part_u, const int* __restrict__ part_r,
                                 int* __restrict__ cur_u, int* __restrict__ cur_r) {
    int b = blockIdx.x;
    int* out;
    int* cur;
    const int* partials;
    int n, lb;
    if (b < NBU_C) { out = off_u; cur = cur_u; partials = part_u; n = NU; lb = b; }
    else           { out = off_r; cur = cur_r; partials = part_r; n = NR; lb = b - NBU_C; }
    int gid = lb * 1024 + threadIdx.x;
    if (gid < n) {
        int v = out[gid] + partials[lb];
        out[gid] = v;
        cur[gid] = v;
    }
}

// ---------------- CSR fill ----------------
__global__ void fill_csr_kernel(const int* __restrict__ e_src, const int* __restrict__ e_dst,
                                int* __restrict__ cur_u, int* __restrict__ cur_r,
                                int* __restrict__ csr_u, int* __restrict__ csr_r, int E) {
    int i = blockIdx.x * blockDim.x + threadIdx.x;
    if (i < E) {
        int s = e_src[i];
        int d = e_dst[i];
        int pr = atomicAdd(&cur_r[d], 1);
        csr_r[pr] = s;
        int pu = atomicAdd(&cur_u[s], 1);
        csr_u[pu] = d;
    }
}

// ---------------- batched fold with optional tf32 pre-rounding ----------------
struct FoldJobs {
    const float* A[4];
    const float* B[4];
    float* C[4];
    int M[4];
    int rnd[4];     // 1 => round output to tf32 (for GEMM B operands)
    int boff[5];
};

__global__ void fold4_kernel(FoldJobs jobs) {
    int bx = blockIdx.x;
    int j = 0;
    while (j < 3 && bx >= jobs.boff[j + 1]) j++;
    const float* A = jobs.A[j];
    const float* B = jobs.B[j];
    float* C = jobs.C[j];
    int M = jobs.M[j];
    int rnd = jobs.rnd[j];
    int m0 = (bx - jobs.boff[j]) * 4;

    __shared__ float sA[4][128];
    int tx = threadIdx.x;
    int ty = threadIdx.y;
    int tid = ty * 64 + tx;
    for (int i = tid; i < 4 * 128; i += 256) {
        int r = i >> 7, k = i & 127;
        sA[r][k] = (m0 + r < M) ? A[(size_t)(m0 + r) * 128 + k] : 0.0f;
    }
    __syncthreads();
    int m = m0 + ty;
    if (m >= M) return;
    float acc0 = 0.f, acc1 = 0.f;
#pragma unroll
    for (int k = 0; k < 128; k += 2) {
        acc0 = fmaf(sA[ty][k], B[k * 64 + tx], acc0);
        acc1 = fmaf(sA[ty][k + 1], B[(k + 1) * 64 + tx], acc1);
    }
    float res = acc0 + acc1;
    if (rnd) {
        uint32_t u = f2tf(res);
        C[(size_t)m * 64 + tx] = __uint_as_float(u);
    } else {
        C[(size_t)m * 64 + tx] = res;
    }
}

// ---------------- fp16 helpers ----------------
__device__ __forceinline__ void acc_add8(float* acc, uint4 x) {
    const __half2* p = reinterpret_cast<const __half2*>(&x);
#pragma unroll
    for (int i = 0; i < 4; i++) {
        float2 f = __half22float2(p[i]);
        acc[2 * i] += f.x;
        acc[2 * i + 1] += f.y;
    }
}

// ---------------- dual-job 64-wide fp16 CSR aggregation, fused epilogues ----------------
template <bool NORM>
__global__ __launch_bounds__(256)
void agg64dual_kernel(const __half* __restrict__ h0, const int* __restrict__ csr0,
                      const int* __restrict__ off0, const int* __restrict__ deg0,
                      const float* __restrict__ cvec0,
                      __half* __restrict__ out0, int n0, int nb0,
                      const __half* __restrict__ h1, const int* __restrict__ csr1,
                      const int* __restrict__ off1, const int* __restrict__ deg1,
                      const float* __restrict__ cvec1,
                      __half* __restrict__ out1, int n1) {
    const __half* h;
    const int *csr, *off, *deg;
    const float *cvec;
    __half* outp;
    int n, gid;
    if ((int)blockIdx.x < nb0) {
        h = h0; csr = csr0; off = off0; deg = deg0; cvec = cvec0;
        outp = out0; n = n0;
        gid = blockIdx.x * 256 + threadIdx.x;
    } else {
        h = h1; csr = csr1; off = off1; deg = deg1; cvec = cvec1;
        outp = out1; n = n1;
        gid = (blockIdx.x - nb0) * 256 + threadIdx.x;
    }
    int node = gid >> 3;
    int lane = gid & 7;
    if (node >= n) return;
    int start = off[node];
    int d = deg[node];
    float acc[8];
#pragma unroll
    for (int i = 0; i < 8; i++) acc[i] = 0.0f;
    int j = 0;
    for (; j + 8 <= d; j += 8) {
        int sx[8];
#pragma unroll
        for (int k = 0; k < 8; k++) sx[k] = __ldg(&csr[start + j + k]);
        uint4 xv[8];
#pragma unroll
        for (int k = 0; k < 8; k++)
            xv[k] = *reinterpret_cast<const uint4*>(h + (size_t)sx[k] * 64 + lane * 8);
#pragma unroll
        for (int k = 0; k < 8; k++) acc_add8(acc, xv[k]);
    }
    for (; j + 4 <= d; j += 4) {
        int sx[4];
#pragma unroll
        for (int k = 0; k < 4; k++) sx[k] = __ldg(&csr[start + j + k]);
        uint4 xv[4];
#pragma unroll
        for (int k = 0; k < 4; k++)
            xv[k] = *reinterpret_cast<const uint4*>(h + (size_t)sx[k] * 64 + lane * 8);
#pragma unroll
        for (int k = 0; k < 4; k++) acc_add8(acc, xv[k]);
    }
    for (; j < d; j++) {
        int s = __ldg(&csr[start + j]);
        uint4 x = *reinterpret_cast<const uint4*>(h + (size_t)s * 64 + lane * 8);
        acc_add8(acc, x);
    }

    float sc = deg_rs(d);
    float cv[8];
    *reinterpret_cast<float4*>(&cv[0]) = *reinterpret_cast<const float4*>(cvec + lane * 8);
    *reinterpret_cast<float4*>(&cv[4]) = *reinterpret_cast<const float4*>(cvec + lane * 8 + 4);

    float v[8];
    if (NORM) {
#pragma unroll
        for (int i = 0; i < 8; i++) v[i] = fmaf(acc[i], sc, cv[i]);
        float ss = 0.0f;
#pragma unroll
        for (int i = 0; i < 8; i++) ss = fmaf(v[i], v[i], ss);
#pragma unroll
        for (int o = 4; o > 0; o >>= 1) ss += __shfl_xor_sync(0xFFFFFFFFu, ss, o, 8);
        float inv = 1.0f / fmaxf(sqrtf(ss), 1e-12f);
#pragma unroll
        for (int i = 0; i < 8; i++) v[i] *= inv;
    } else {
        float sc2 = sc * sc;
#pragma unroll
        for (int i = 0; i < 8; i++) v[i] = fmaf(acc[i], sc2, cv[i] * sc);
    }
    uint4 pk;
    __half2* hp = reinterpret_cast<__half2*>(&pk);
#pragma unroll
    for (int i = 0; i < 4; i++) hp[i] = __floats2half2_rn(v[2 * i], v[2 * i + 1]);
    *reinterpret_cast<uint4*>(outp + (size_t)node * 64 + lane * 8) = pk;
}

// ---------------- TF32 tensor-core GEMM, dual-job, 3-stage pipeline ----------------
// W is tf32-PRE-ROUNDED (fold does cvt.rna once); B fragments are raw bit loads.
#define MMA_TF32(c, a, bq)                                                     \
    asm volatile("mma.sync.aligned.m16n8k8.row.col.f32.tf32.tf32.f32 "        \
                 "{%0,%1,%2,%3}, {%4,%5,%6,%7}, {%8,%9}, {%0,%1,%2,%3};"      \
                 : "+f"(c[0]), "+f"(c[1]), "+f"(c[2]), "+f"(c[3])             \
                 : "r"(a[0]), "r"(a[1]), "r"(a[2]), "r"(a[3]),                \
                   "r"(bq[0]), "r"(bq[1]))

#define GEMM_BN 64
#define GEMM_BM 128
#define GEMM_BK 16
#define GEMM_WN 32
#define GEMM_NT 4
#define GEMM_ASTR 20
#define GEMM_BSTR 72
#define GEMM_STAGES 3

#define ISSUE_TILE(s, k0)                                                          \
    {                                                                              \
        uint32_t da = (uint32_t)__cvta_generic_to_shared(                          \
            &As[s][arow * GEMM_ASTR + akoff]);                                     \
        const float* sa = gA + (k0) + akoff;                                       \
        asm volatile("cp.async.ca.shared.global [%0], [%1], 16;" ::"r"(da),        \
                     "l"(sa));                                                     \
        asm volatile("cp.async.ca.shared.global [%0], [%1], 16;" ::"r"(da + 16),   \
                     "l"(sa + 4));                                                 \
        uint32_t db = (uint32_t)__cvta_generic_to_shared(                          \
            &Bs[s][wkr * GEMM_BSTR + wn4]);                                        \
        const float* sb = W + (size_t)((k0) + wkr) * GEMM_BN + wn4;                \
        asm volatile("cp.async.ca.shared.global [%0], [%1], 16;" ::"r"(db),        \
                     "l"(sb));                                                     \
        asm volatile("cp.async.commit_group;");                                    \
    }

template <int NSTEPS>
__device__ __forceinline__ void gemm_core(
    float (*As)[GEMM_BM * GEMM_ASTR], float (*Bs)[GEMM_BK * GEMM_BSTR],
    const float* __restrict__ A, const float* __restrict__ W,
    const float* __restrict__ bias, const int* __restrict__ deg,
    __half* __restrict__ C, int M, int by) {
    constexpr int K = NSTEPS * GEMM_BK;
    const int tid = threadIdx.x;
    const int lane = tid & 31;
    const int warp = tid >> 5;
    const int wm = warp & 3;
    const int wn = warp >> 2;
    const int row0 = by * GEMM_BM;

    const int arow = tid >> 1;
    const int akoff = (tid & 1) * 8;
    int garow = row0 + arow;
    if (garow > M - 1) garow = M - 1;
    const float* gA = A + (size_t)garow * K;

    const int wkr = tid >> 4;
    const int wn4 = (tid & 15) * 4;

    float cacc[2][GEMM_NT][4];
#pragma unroll
    for (int mt = 0; mt < 2; mt++)
#pragma unroll
        for (int nt = 0; nt < GEMM_NT; nt++)
#pragma unroll
            for (int q = 0; q < 4; q++) cacc[mt][nt][q] = 0.0f;

    ISSUE_TILE(0, 0);
    ISSUE_TILE(1, GEMM_BK);
    asm volatile("cp.async.wait_group 1;");
    __syncthreads();

    const int fr = lane >> 2;
    const int fk = lane & 3;

    // hoisted fragment smem offsets
    const int aoff0 = (wm * 32 + fr) * GEMM_ASTR + fk;       // mt=0
    const int aoff1 = aoff0 + 16 * GEMM_ASTR;                // mt=1
    const int boff = fk * GEMM_BSTR + wn * GEMM_WN + fr;

#pragma unroll 4
    for (int t = 0; t < NSTEPS; t++) {
        int s = t % GEMM_STAGES;
        if (t + 2 < NSTEPS) {
            int sn = (t + 2) % GEMM_STAGES;
            ISSUE_TILE(sn, (t + 2) * GEMM_BK);
        }

#pragma unroll
        for (int kk = 0; kk < 2; kk++) {
            int kb = kk * 8;
            uint32_t af[2][4];
            const float* as = &As[s][kb];
            af[0][0] = f2tf(as[aoff0]);
            af[0][1] = f2tf(as[aoff0 + 8 * GEMM_ASTR]);
            af[0][2] = f2tf(as[aoff0 + 4]);
            af[0][3] = f2tf(as[aoff0 + 8 * GEMM_ASTR + 4]);
            af[1][0] = f2tf(as[aoff1]);
            af[1][1] = f2tf(as[aoff1 + 8 * GEMM_ASTR]);
            af[1][2] = f2tf(as[aoff1 + 4]);
            af[1][3] = f2tf(as[aoff1 + 8 * GEMM_ASTR + 4]);
            uint32_t bf[GEMM_NT][2];
            const uint32_t* bs = reinterpret_cast<const uint32_t*>(&Bs[s][kb * GEMM_BSTR]);
#pragma unroll
            for (int nt = 0; nt < GEMM_NT; nt++) {
                bf[nt][0] = bs[boff + nt * 8];                     // pre-rounded: raw load
                bf[nt][1] = bs[boff + nt * 8 + 4 * GEMM_BSTR];
            }
#pragma unroll
            for (int mt = 0; mt < 2; mt++)
#pragma unroll
                for (int nt = 0; nt < GEMM_NT; nt++) MMA_TF32(cacc[mt][nt], af[mt], bf[nt]);
        }

        if (t + 2 < NSTEPS) {
            asm volatile("cp.async.wait_group 1;");
            __syncthreads();
        } else if (t + 1 < NSTEPS) {
            asm volatile("cp.async.wait_group 0;");
            __syncthreads();
        }
    }

#pragma unroll
    for (int mt = 0; mt < 2; mt++) {
        int r0 = row0 + wm * 32 + mt * 16 + fr;
        int r1 = r0 + 8;
        float s0 = (r0 < M) ? deg_rs(deg[r0]) : 0.0f;
        float s1 = (r1 < M) ? deg_rs(deg[r1]) : 0.0f;
#pragma unroll
        for (int nt = 0; nt < GEMM_NT; nt++) {
            int cb = wn * GEMM_WN + nt * 8 + (lane & 3) * 2;
            float2 bv = *reinterpret_cast<const float2*>(bias + cb);
            if (r0 < M) {
                __half2 hv = __floats2half2_rn((cacc[mt][nt][0] + bv.x) * s0,
                                               (cacc[mt][nt][1] + bv.y) * s0);
                *reinterpret_cast<__half2*>(C + (size_t)r0 * GEMM_BN + cb) = hv;
            }
            if (r1 < M) {
                __half2 hv = __floats2half2_rn((cacc[mt][nt][2] + bv.x) * s1,
                                               (cacc[mt][nt][3] + bv.y) * s1);
                *reinterpret_cast<__half2*>(C + (size_t)r1 * GEMM_BN + cb) = hv;
            }
        }
    }
}

__global__ __launch_bounds__(256)
void mma_gemm64h_dual_kernel(
    const float* __restrict__ A0, const float* __restrict__ W0,
    const float* __restrict__ bias0, const int* __restrict__ deg0,
    __half* __restrict__ C0, int M0, int nby0,
    const float* __restrict__ A1, const float* __restrict__ W1,
    const float* __restrict__ bias1, const int* __restrict__ deg1,
    __half* __restrict__ C1, int M1) {
    __shared__ float As[GEMM_STAGES][GEMM_BM * GEMM_ASTR];
    __shared__ float Bs[GEMM_STAGES][GEMM_BK * GEMM_BSTR];
    if ((int)blockIdx.y < nby0) {
        gemm_core<IN_U / GEMM_BK>(As, Bs, A0, W0, bias0, deg0, C0, M0, blockIdx.y);
    } else {
        gemm_core<IN_R / GEMM_BK>(As, Bs, A1, W1, bias1, deg1, C1, M1, blockIdx.y - nby0);
    }
}
#undef ISSUE_TILE

// ---------------- merged pair-dot (fp16 inputs), 4 lanes/pair ----------------
__global__ __launch_bounds__(256)
void pairdot2_kernel(const __half* __restrict__ nu, const __half* __restrict__ nr,
                     const int* __restrict__ pos_u, const int* __restrict__ pos_r,
                     const int* __restrict__ neg_u, const int* __restrict__ neg_r,
                     float* __restrict__ out) {
    int gid = blockIdx.x * blockDim.x + threadIdx.x;
    int p = gid >> 2;
    int lane = gid & 3;
    if (p >= EP + EN) return;
    int u, r;
    if (p < EP) { u = __ldg(&pos_u[p]); r = __ldg(&pos_r[p]); }
    else        { u = __ldg(&neg_u[p - EP]); r = __ldg(&neg_r[p - EP]); }
    const __half* pa = nu + (size_t)u * 64 + lane * 16;
    const __half* pc = nr + (size_t)r * 64 + lane * 16;
    uint4 a0 = *reinterpret_cast<const uint4*>(pa);
    uint4 a1 = *reinterpret_cast<const uint4*>(pa + 8);
    uint4 c0 = *reinterpret_cast<const uint4*>(pc);
    uint4 c1 = *reinterpret_cast<const uint4*>(pc + 8);
    const __half2* a2 = reinterpret_cast<const __half2*>(&a0);
    const __half2* a3 = reinterpret_cast<const __half2*>(&a1);
    const __half2* c2 = reinterpret_cast<const __half2*>(&c0);
    const __half2* c3 = reinterpret_cast<const __half2*>(&c1);
    float d = 0.0f;
#pragma unroll
    for (int i = 0; i < 4; i++) {
        float2 fa = __half22float2(a2[i]);
        float2 fc = __half22float2(c2[i]);
        d = fmaf(fa.x, fc.x, d);
        d = fmaf(fa.y, fc.y, d);
    }
#pragma unroll
    for (int i = 0; i < 4; i++) {
        float2 fa = __half22float2(a3[i]);
        float2 fc = __half22float2(c3[i]);
        d = fmaf(fa.x, fc.x, d);
        d = fmaf(fa.y, fc.y, d);
    }
#pragma unroll
    for (int o = 2; o > 0; o >>= 1) d += __shfl_xor_sync(0xFFFFFFFFu, d, o, 4);
    if (lane == 0) out[p] = d;
}

// ---------------- host launch ----------------
extern "C" void kernel_launch(void* const* d_in, const int* in_sizes, int n_in,
                              void* d_out, int out_size) {
    const float* user_feat = (const float*)d_in[0];
    const float* repo_feat = (const float*)d_in[1];
    const float* W_u   = (const float*)d_in[2];
    const float* b_u   = (const float*)d_in[3];
    const float* W_rp  = (const float*)d_in[4];
    const float* b_rp  = (const float*)d_in[5];
    const float* W1_ur = (const float*)d_in[6];
    const float* b1_ur = (const float*)d_in[7];
    const float* W1_ru = (const float*)d_in[8];
    const float* b1_ru = (const float*)d_in[9];
    const float* W2_ur = (const float*)d_in[10];
    const float* b2_ur = (const float*)d_in[11];
    const float* W2_ru = (const float*)d_in[12];
    const float* b2_ru = (const float*)d_in[13];
    const int* e_src = (const int*)d_in[14];
    const int* e_dst = (const int*)d_in[15];
    const int* pos_u = (const int*)d_in[16];
    const int* pos_r = (const int*)d_in[17];
    const int* neg_u = (const int*)d_in[18];
    const int* neg_r = (const int*)d_in[19];
    float* out = (float*)d_out;

    void* q[24];
    cudaGetSymbolAddress(&q[0],  g_spu);
    cudaGetSymbolAddress(&q[1],  g_spr);
    cudaGetSymbolAddress(&q[2],  g_st2_repo);
    cudaGetSymbolAddress(&q[3],  g_st2_user);
    cudaGetSymbolAddress(&q[4],  g_h2_user);
    cudaGetSymbolAddress(&q[5],  g_h2_repo);
    cudaGetSymbolAddress(&q[6],  g_deg_u);
    cudaGetSymbolAddress(&q[7],  g_deg_r);
    cudaGetSymbolAddress(&q[8],  g_off_u);
    cudaGetSymbolAddress(&q[9],  g_off_r);
    cudaGetSymbolAddress(&q[10], g_cur_u);
    cudaGetSymbolAddress(&q[11], g_cur_r);
    cudaGetSymbolAddress(&q[12], g_csr_u);
    cudaGetSymbolAddress(&q[13], g_csr_r);
    cudaGetSymbolAddress(&q[14], g_part_u);
    cudaGetSymbolAddress(&q[15], g_part_r);
    cudaGetSymbolAddress(&q[16], g_T2);
    cudaGetSymbolAddress(&q[17], g_Wfu2);
    cudaGetSymbolAddress(&q[18], g_Wfr);
    cudaGetSymbolAddress(&q[19], g_Wfpr);
    cudaGetSymbolAddress(&q[20], g_c0r);
    cudaGetSymbolAddress(&q[21], g_c0u);
    cudaGetSymbolAddress(&q[22], g_c1r);
    cudaGetSymbolAddress(&q[23], g_bfpr);

    __half* spu      = (__half*)q[0];
    __half* spr      = (__half*)q[1];
    __half* st2_repo = (__half*)q[2];
    __half* st2_user = (__half*)q[3];
    __half* h2_user  = (__half*)q[4];
    __half* h2_repo  = (__half*)q[5];
    int*    deg_u   = (int*)q[6];
    int*    deg_r   = (int*)q[7];
    int*    off_u   = (int*)q[8];
    int*    off_r   = (int*)q[9];
    int*    cur_u   = (int*)q[10];
    int*    cur_r   = (int*)q[11];
    int*    csr_u   = (int*)q[12];
    int*    csr_r   = (int*)q[13];
    int*    part_u  = (int*)q[14];
    int*    part_r  = (int*)q[15];
    float*  T2      = (float*)q[16];
    float*  Wfu2    = (float*)q[17];
    float*  Wfr     = (float*)q[18];
    float*  Wfpr    = (float*)q[19];
    float*  c0r     = (float*)q[20];
    float*  c0u     = (float*)q[21];
    float*  c1r     = (float*)q[22];
    float*  bfpr    = (float*)q[23];

    cudaStream_t s2 = g_hx.s2;

    // ===== fork side stream =====
    cudaEventRecord(g_hx.evFork, 0);
    cudaStreamWaitEvent(s2, g_hx.evFork, 0);

    // ---- side stream: weight/bias folds (Wfr/Wfpr tf32 pre-rounded) ----
    {
        FoldJobs ja;
        ja.A[0] = W1_ur; ja.B[0] = W2_ru; ja.C[0] = T2;   ja.M[0] = D0; ja.rnd[0] = 0;
        ja.A[1] = W1_ru; ja.B[1] = W2_ur; ja.C[1] = Wfu2; ja.M[1] = D0; ja.rnd[1] = 0;
        ja.A[2] = b1_ur; ja.B[2] = W2_ru; ja.C[2] = c0r;  ja.M[2] = 1;  ja.rnd[2] = 0;
        ja.A[3] = b1_ru; ja.B[3] = W2_ur; ja.C[3] = c0u;  ja.M[3] = 1;  ja.rnd[3] = 0;
        ja.boff[0] = 0; ja.boff[1] = 32; ja.boff[2] = 64; ja.boff[3] = 65; ja.boff[4] = 66;
        fold4_kernel<<<66, dim3(64, 4), 0, s2>>>(ja);

        FoldJobs jb;
        jb.A[0] = W_u;  jb.B[0] = T2;   jb.C[0] = Wfr;  jb.M[0] = IN_U; jb.rnd[0] = 1;
        jb.A[1] = b_u;  jb.B[1] = T2;   jb.C[1] = c1r;  jb.M[1] = 1;    jb.rnd[1] = 0;
        jb.A[2] = W_rp; jb.B[2] = Wfu2; jb.C[2] = Wfpr; jb.M[2] = IN_R; jb.rnd[2] = 1;
        jb.A[3] = b_rp; jb.B[3] = Wfu2; jb.C[3] = bfpr; jb.M[3] = 1;    jb.rnd[3] = 0;
        jb.boff[0] = 0; jb.boff[1] = 32; jb.boff[2] = 33; jb.boff[3] = 97; jb.boff[4] = 98;
        fold4_kernel<<<98, dim3(64, 4), 0, s2>>>(jb);
    }

    // ---- main stream: degrees only ----
    cudaMemsetAsync(deg_u, 0, NU * sizeof(int), 0);
    cudaMemsetAsync(deg_r, 0, NR * sizeof(int), 0);
    count_deg_kernel<<<(NE / 2 + 255) / 256, 256>>>(e_src, e_dst, deg_u, deg_r);
    cudaEventRecord(g_hx.evDeg, 0);

    // ---- side stream: merged projections (single launch; rs inlined from deg) ----
    cudaStreamWaitEvent(s2, g_hx.evDeg, 0);
    mma_gemm64h_dual_kernel<<<dim3(1, GYU_C + GYR_C), 256, 0, s2>>>(
        user_feat, Wfr, c1r, deg_u, spu, NU, GYU_C,
        repo_feat, Wfpr, bfpr, deg_r, spr, NR);
    cudaEventRecord(g_hx.evGemm, s2);

    // ---- main stream (concurrent): CSR build ----
    scan_blocks2_kernel<<<NBU_C + NBR_C, 1024>>>(deg_u, deg_r, off_u, off_r, part_u, part_r);
    scan_partials2_kernel<<<2, 128>>>(part_u, part_r);
    scan_add2_kernel<<<NBU_C + NBR_C, 1024>>>(off_u, off_r, part_u, part_r, cur_u, cur_r);
    fill_csr_kernel<<<(NE + 255) / 256, 256>>>(e_src, e_dst, cur_u, cur_r, csr_u, csr_r, NE);

    // ===== join =====
    cudaStreamWaitEvent(0, g_hx.evGemm, 0);

    // ---- layer-1 dual aggregation ----
    {
        int nb0 = (NR * 8 + 255) / 256;
        int nb1 = (NU * 8 + 255) / 256;
        agg64dual_kernel<false><<<nb0 + nb1, 256>>>(
            spu, csr_r, off_r, deg_r, c0r, st2_repo, NR, nb0,
            spr, csr_u, off_u, deg_u, c0u, st2_user, NU);
    }

    // ---- layer-2 dual aggregation with fused bias + L2norm ----
    {
        int nb0 = (NR * 8 + 255) / 256;
        int nb1 = (NU * 8 + 255) / 256;
        agg64dual_kernel<true><<<nb0 + nb1, 256>>>(
            st2_user, csr_r, off_r, deg_r, b2_ur, h2_repo, NR, nb0,
            st2_repo, csr_u, off_u, deg_u, b2_ru, h2_user, NU);
    }

    // ---- merged pair dots (4 lanes/pair) ----
    pairdot2_kernel<<<((EP + EN) * 4 + 255) / 256, 256>>>(h2_user, h2_repo,
                                                          pos_u, pos_r, neg_u, neg_r, out);
}